// round 10
// baseline (speedup 1.0000x reference)
#include <cuda_runtime.h>
#include <cuda_fp16.h>
#include <math.h>

#define B_   64
#define L_   32
#define D_   1024
#define DFF  2048
#define K_   128
#define N_   256

// ---------------- scratch (no allocations allowed) ----------------
__device__ float g_A[N_ * N_];
__device__ float g_W[N_ * K_ * K_];      // UNNORMALIZED Wl
__device__ float g_winv[N_ * K_];
__device__ float g_wpart[8][N_ * K_];
__device__ float g_xr[B_ * N_ * K_];
__device__ float g_xloc[B_ * N_ * K_];
__device__ float g_xln[B_ * K_ * N_];
__device__ float g_mixed[B_ * L_ * D_];
__device__ float g_H[B_ * L_ * DFF];
__device__ float g_ffn[B_ * L_ * D_];

// ---------------- helpers ----------------
__device__ __forceinline__ void blockReduce2_256(float& s1, float& s2) {
    __shared__ float sh1[8], sh2[8];
    int t = threadIdx.x;
    #pragma unroll
    for (int o = 16; o > 0; o >>= 1) {
        s1 += __shfl_xor_sync(0xffffffffu, s1, o);
        s2 += __shfl_xor_sync(0xffffffffu, s2, o);
    }
    if ((t & 31) == 0) { sh1[t >> 5] = s1; sh2[t >> 5] = s2; }
    __syncthreads();
    float a = 0.f, b = 0.f;
    #pragma unroll
    for (int w = 0; w < 8; w++) { a += sh1[w]; b += sh2[w]; }
    s1 = a; s2 = b;
    __syncthreads();
}

__device__ __forceinline__ unsigned pack16(float x0, float x1) {
    unsigned h;
    asm("cvt.rn.f16x2.f32 %0, %1, %2;" : "=r"(h) : "f"(x1), "f"(x0));
    return h;
}

__device__ __forceinline__ void mma16816(float* c, const unsigned* a, unsigned b0, unsigned b1) {
    asm volatile(
        "mma.sync.aligned.m16n8k16.row.col.f32.f16.f16.f32 "
        "{%0,%1,%2,%3}, {%4,%5,%6,%7}, {%8,%9}, {%0,%1,%2,%3};"
        : "+f"(c[0]), "+f"(c[1]), "+f"(c[2]), "+f"(c[3])
        : "r"(a[0]), "r"(a[1]), "r"(a[2]), "r"(a[3]), "r"(b0), "r"(b1));
}

// ---------------- K0: A = A_logits / max(||col||, eps) ----------------
__global__ void k_prepA(const float* __restrict__ Al) {
    int j = blockIdx.x;
    int i = threadIdx.x;
    float v = Al[i * N_ + j];
    float s1 = v * v, s2 = 0.f;
    blockReduce2_256(s1, s2);
    float inv = 1.f / fmaxf(sqrtf(s1), 1e-12f);
    g_A[i * N_ + j] = v * inv;
}

// ---------------- prepW ----------------
__global__ void k_prepW1(const float* __restrict__ W1, const float* __restrict__ WV) {
    int tt = blockIdx.x;
    int is = blockIdx.y;
    int o  = threadIdx.x;
    __shared__ float w1s[16][8];
    w1s[o >> 3][o & 7] = W1[(tt * 16 + (o >> 3)) * 8 + (o & 7)];
    __syncthreads();
    float ss[16];
    #pragma unroll
    for (int tl = 0; tl < 16; tl++) ss[tl] = 0.f;
    for (int ii = 0; ii < 16; ii++) {
        int i = is * 16 + ii;
        float wv[8];
        #pragma unroll
        for (int k = 0; k < 8; k++) wv[k] = WV[((size_t)k * K_ + i) * K_ + o];
        #pragma unroll
        for (int tl = 0; tl < 16; tl++) {
            float wl = 0.f;
            #pragma unroll
            for (int k = 0; k < 8; k++) wl += w1s[tl][k] * wv[k];
            ss[tl] += wl * wl;
            g_W[((size_t)(tt * 16 + tl) * K_ + i) * K_ + o] = wl;
        }
    }
    #pragma unroll
    for (int tl = 0; tl < 16; tl++)
        g_wpart[is][(tt * 16 + tl) * K_ + o] = ss[tl];
}

__global__ void k_prepWinv() {
    int t = blockIdx.x;
    int o = threadIdx.x;
    float ss = 0.f;
    #pragma unroll
    for (int s = 0; s < 8; s++) ss += g_wpart[s][t * K_ + o];
    g_winv[t * K_ + o] = 1.f / fmaxf(sqrtf(ss), 1e-12f);
}

// ---------------- K2: xr = LN128( x + LN_D(y) )  [prefetched] ----------------
__global__ void k_xr(const float* __restrict__ x, const float* __restrict__ y,
                     const float* __restrict__ nyg, const float* __restrict__ nyb,
                     const float* __restrict__ kn1g, const float* __restrict__ kn1b) {
    int row = blockIdx.x;
    int t = threadIdx.x;
    float4 yv4 = *(const float4*)(y + (size_t)row * D_ + t * 4);
    float4 xv4 = *(const float4*)(x + (size_t)row * D_ + t * 4);   // prefetch
    float yv[4] = {yv4.x, yv4.y, yv4.z, yv4.w};
    float xv[4] = {xv4.x, xv4.y, xv4.z, xv4.w};
    float s1 = 0.f, s2 = 0.f;
    #pragma unroll
    for (int e = 0; e < 4; e++) { s1 += yv[e]; s2 += yv[e] * yv[e]; }
    blockReduce2_256(s1, s2);
    float m = s1 * (1.f / D_);
    float var = s2 * (1.f / D_) - m * m;
    float rs = rsqrtf(var + 1e-5f);
    float kin[4];
    float ls1 = 0.f, ls2 = 0.f;
    #pragma unroll
    for (int e = 0; e < 4; e++) {
        int d = t * 4 + e;
        float ny = (yv[e] - m) * rs * nyg[d] + nyb[d];
        float kv = xv[e] + ny;
        kin[e] = kv; ls1 += kv; ls2 += kv * kv;
    }
    #pragma unroll
    for (int o = 16; o > 0; o >>= 1) {
        ls1 += __shfl_xor_sync(0xffffffffu, ls1, o);
        ls2 += __shfl_xor_sync(0xffffffffu, ls2, o);
    }
    float lm = ls1 * (1.f / 128.f);
    float lv = ls2 * (1.f / 128.f) - lm * lm;
    float lrs = rsqrtf(lv + 1e-5f);
    #pragma unroll
    for (int e = 0; e < 4; e++) {
        int d = t * 4 + e;
        int i = d & 127;
        g_xr[(size_t)row * D_ + d] = (kin[e] - lm) * lrs * kn1g[i] + kn1b[i];
    }
}

// ---------------- K4a: transpose + LN over N (kn2) ----------------
__global__ void k_trln(const float* __restrict__ kn2g, const float* __restrict__ kn2b) {
    int k0 = blockIdx.x * 32;
    int b  = blockIdx.y;
    int t  = threadIdx.x;
    __shared__ float tr[32][264];
    __shared__ float mm[32], rr[32];
    for (int q = t; q < 2048; q += 256) {
        int n = q >> 3, f = q & 7;
        float4 v = *(const float4*)&g_xloc[((size_t)b * N_ + n) * K_ + k0 + f * 4];
        tr[f * 4 + 0][n] = v.x; tr[f * 4 + 1][n] = v.y;
        tr[f * 4 + 2][n] = v.z; tr[f * 4 + 3][n] = v.w;
    }
    __syncthreads();
    int k = t >> 3, s = t & 7;
    float s1 = 0.f, s2 = 0.f;
    #pragma unroll 8
    for (int j = 0; j < 32; j++) {
        float v = tr[k][s + 8 * j];
        s1 += v; s2 += v * v;
    }
    #pragma unroll
    for (int off = 4; off > 0; off >>= 1) {
        s1 += __shfl_xor_sync(0xffffffffu, s1, off);
        s2 += __shfl_xor_sync(0xffffffffu, s2, off);
    }
    if (s == 0) {
        float m = s1 * (1.f / N_);
        float var = s2 * (1.f / N_) - m * m;
        mm[k] = m; rr[k] = rsqrtf(var + 1e-5f);
    }
    __syncthreads();
    int n2 = t;
    float gn = kn2g[n2], bn = kn2b[n2];
    #pragma unroll 4
    for (int kk = 0; kk < 32; kk++) {
        float v = (tr[kk][n2] - mm[kk]) * rr[kk] * gn + bn;
        g_xln[((size_t)b * K_ + k0 + kk) * N_ + n2] = v;
    }
}

// ---------------- generic cp.async pipelined fp16 tensor-core GEMM ----------------
// mode 1: down  A=g_H(l) [64x2048] @ W0(l)[2048x128tile] -> g_ffn
// mode 3: xloc  A=g_xr(:,n,:) [64x128] @ g_W(n)[128x128], scale g_winv(n) -> g_xloc
#define STAGES   4
#define STG_AW   40
#define STG_BW   132
#define STG_AB   10240
#define STG_BYTES 27136
#define GEMM_SMEM (STAGES * STG_BYTES)

__global__ __launch_bounds__(256, 2) void k_gemm(const float* __restrict__ W0, int mode) {
    extern __shared__ float sm[];
    unsigned smem_u32 = (unsigned)__cvta_generic_to_shared(sm);

    int bx  = blockIdx.x;
    int nt0 = blockIdx.y * 128;
    int t   = threadIdx.x;

    const float* Ap; long lda, ostride; int Kdim, width;
    const float* Bp; float* Op; const float* sc = 0;
    if (mode == 1) {
        Ap = g_H + (size_t)bx * DFF;  lda = (long)L_ * DFF; Kdim = DFF; width = D_;
        Bp = W0 + (size_t)bx * DFF * D_ + nt0;
        Op = g_ffn + (size_t)bx * D_ + nt0;
        ostride = (long)L_ * D_;
    } else {
        Ap = g_xr + (size_t)bx * K_; lda = (long)N_ * K_; Kdim = K_; width = K_;
        Bp = g_W + (size_t)bx * K_ * K_;
        Op = g_xloc + (size_t)bx * K_;
        ostride = (long)N_ * K_;
        sc = g_winv + (size_t)bx * K_;
    }
    int nit = Kdim / 32;

    int lane = t & 31, wid = t >> 5;
    int g = lane >> 2, tg = lane & 3;
    int wm = (wid & 1) * 32;
    int wn = (wid >> 1) * 32;

    float acc[2][4][4];
    #pragma unroll
    for (int mt = 0; mt < 2; mt++)
        #pragma unroll
        for (int nt = 0; nt < 4; nt++)
            #pragma unroll
            for (int e = 0; e < 4; e++) acc[mt][nt][e] = 0.f;

    auto issue = [&](int s) {
        if (s < nit) {
            int k0 = s * 32;
            unsigned base = smem_u32 + (s % STAGES) * STG_BYTES;
            #pragma unroll
            for (int i = 0; i < 2; i++) {
                int q = t + i * 256;
                int m = q >> 3, f4 = q & 7;
                unsigned dst = base + (unsigned)(m * STG_AW + f4 * 4) * 4u;
                const float* src = Ap + (size_t)m * lda + k0 + f4 * 4;
                asm volatile("cp.async.cg.shared.global [%0], [%1], 16;" :: "r"(dst), "l"(src));
            }
            #pragma unroll
            for (int i = 0; i < 4; i++) {
                int q = t + i * 256;
                int k = q >> 5, n4 = (q & 31) * 4;
                unsigned dst = base + STG_AB + (unsigned)(k * STG_BW + n4) * 4u;
                const float* src = Bp + (size_t)(k0 + k) * width + n4;
                asm volatile("cp.async.cg.shared.global [%0], [%1], 16;" :: "r"(dst), "l"(src));
            }
        }
        asm volatile("cp.async.commit_group;");
    };

    issue(0); issue(1); issue(2);

    for (int it = 0; it < nit; it++) {
        asm volatile("cp.async.wait_group 2;");
        __syncthreads();
        issue(it + 3);

        const float* Af = sm + (size_t)(it % STAGES) * (STG_BYTES / 4);
        const float* Bf = Af + STG_AB / 4;

        #pragma unroll
        for (int s = 0; s < 2; s++) {
            int kp0 = s * 8 + tg, kp1 = kp0 + 4;
            unsigned af[2][4];
            #pragma unroll
            for (int mt = 0; mt < 2; mt++) {
                int r0 = wm + mt * 16 + g, r1 = r0 + 8;
                float2 a00 = *(const float2*)&Af[r0 * STG_AW + 2 * kp0];
                float2 a10 = *(const float2*)&Af[r1 * STG_AW + 2 * kp0];
                float2 a01 = *(const float2*)&Af[r0 * STG_AW + 2 * kp1];
                float2 a11 = *(const float2*)&Af[r1 * STG_AW + 2 * kp1];
                af[mt][0] = pack16(a00.x, a00.y);
                af[mt][1] = pack16(a10.x, a10.y);
                af[mt][2] = pack16(a01.x, a01.y);
                af[mt][3] = pack16(a11.x, a11.y);
            }
            #pragma unroll
            for (int nt = 0; nt < 4; nt++) {
                int cn = wn + nt * 8 + g;
                unsigned b0 = pack16(Bf[(2 * kp0) * STG_BW + cn], Bf[(2 * kp0 + 1) * STG_BW + cn]);
                unsigned b1 = pack16(Bf[(2 * kp1) * STG_BW + cn], Bf[(2 * kp1 + 1) * STG_BW + cn]);
                mma16816(acc[0][nt], af[0], b0, b1);
                mma16816(acc[1][nt], af[1], b0, b1);
            }
        }
        __syncthreads();
    }

    #pragma unroll
    for (int mt = 0; mt < 2; mt++) {
        int r0 = wm + mt * 16 + g;
        #pragma unroll
        for (int nt = 0; nt < 4; nt++) {
            int c = wn + nt * 8 + tg * 2;
            float v0 = acc[mt][nt][0], v1 = acc[mt][nt][1];
            float v2 = acc[mt][nt][2], v3 = acc[mt][nt][3];
            if (sc) {
                float s0 = sc[c], s1v = sc[c + 1];
                v0 *= s0; v1 *= s1v; v2 *= s0; v3 *= s1v;
            }
            float* p0 = Op + (size_t)r0 * ostride + c;
            float* p1 = Op + (size_t)(r0 + 8) * ostride + c;
            *(float2*)p0 = make_float2(v0, v1);
            *(float2*)p1 = make_float2(v2, v3);
        }
    }
}

// ---------------- fused xglob GEMM + mix + LN(n1) -> g_mixed ----------------
// block bx: b = bx/2, k-rows (bx%2)*64..+64 of x_global, ALL 256 n cols.
// epilogue: 16 complete mixed rows l = 16*(bx%2)+lg.
#define XG_BW   260
#define XG_AB   10240
#define XG_STG  43520
#define XG_SMEM (4 * XG_STG)

__global__ __launch_bounds__(256, 1) void k_xgmix(const float* __restrict__ x,
                                                  const float* __restrict__ n1g,
                                                  const float* __restrict__ n1b) {
    extern __shared__ float sm[];
    unsigned smem_u32 = (unsigned)__cvta_generic_to_shared(sm);
    __shared__ float mmv[16], rrv[16];

    int bx = blockIdx.x;          // 128
    int t  = threadIdx.x;
    const float* Ap = g_xln + (size_t)bx * 64 * N_;
    int b = bx >> 1, lbase = (bx & 1) * 16;
    const int nit = N_ / 32;      // 8

    int lane = t & 31, wid = t >> 5;
    int g = lane >> 2, tg = lane & 3;
    int wm = (wid & 1) * 32;
    int wn = (wid >> 1) * 64;     // 4 n-groups of 64 over 256 cols

    float acc[2][8][4];
    #pragma unroll
    for (int mt = 0; mt < 2; mt++)
        #pragma unroll
        for (int nt = 0; nt < 8; nt++)
            #pragma unroll
            for (int e = 0; e < 4; e++) acc[mt][nt][e] = 0.f;

    auto issue = [&](int s) {
        if (s < nit) {
            int k0 = s * 32;
            unsigned base = smem_u32 + (s % STAGES) * XG_STG;
            #pragma unroll
            for (int i = 0; i < 2; i++) {
                int q = t + i * 256;
                int m = q >> 3, f4 = q & 7;
                unsigned dst = base + (unsigned)(m * STG_AW + f4 * 4) * 4u;
                const float* src = Ap + (size_t)m * N_ + k0 + f4 * 4;
                asm volatile("cp.async.cg.shared.global [%0], [%1], 16;" :: "r"(dst), "l"(src));
            }
            #pragma unroll
            for (int i = 0; i < 8; i++) {
                int q = t + i * 256;
                int k = q >> 6, n4 = (q & 63) * 4;
                unsigned dst = base + XG_AB + (unsigned)(k * XG_BW + n4) * 4u;
                const float* src = g_A + (size_t)(k0 + k) * N_ + n4;
                asm volatile("cp.async.cg.shared.global [%0], [%1], 16;" :: "r"(dst), "l"(src));
            }
        }
        asm volatile("cp.async.commit_group;");
    };

    issue(0); issue(1); issue(2);

    for (int it = 0; it < nit; it++) {
        asm volatile("cp.async.wait_group 2;");
        __syncthreads();
        issue(it + 3);

        const float* Af = sm + (size_t)(it % STAGES) * (XG_STG / 4);
        const float* Bf = Af + XG_AB / 4;

        #pragma unroll
        for (int s = 0; s < 2; s++) {
            int kp0 = s * 8 + tg, kp1 = kp0 + 4;
            unsigned af[2][4];
            #pragma unroll
            for (int mt = 0; mt < 2; mt++) {
                int r0 = wm + mt * 16 + g, r1 = r0 + 8;
                float2 a00 = *(const float2*)&Af[r0 * STG_AW + 2 * kp0];
                float2 a10 = *(const float2*)&Af[r1 * STG_AW + 2 * kp0];
                float2 a01 = *(const float2*)&Af[r0 * STG_AW + 2 * kp1];
                float2 a11 = *(const float2*)&Af[r1 * STG_AW + 2 * kp1];
                af[mt][0] = pack16(a00.x, a00.y);
                af[mt][1] = pack16(a10.x, a10.y);
                af[mt][2] = pack16(a01.x, a01.y);
                af[mt][3] = pack16(a11.x, a11.y);
            }
            #pragma unroll
            for (int nt = 0; nt < 8; nt++) {
                int cn = wn + nt * 8 + g;
                unsigned b0 = pack16(Bf[(2 * kp0) * XG_BW + cn], Bf[(2 * kp0 + 1) * XG_BW + cn]);
                unsigned b1 = pack16(Bf[(2 * kp1) * XG_BW + cn], Bf[(2 * kp1 + 1) * XG_BW + cn]);
                mma16816(acc[0][nt], af[0], b0, b1);
                mma16816(acc[1][nt], af[1], b0, b1);
            }
        }
        __syncthreads();
    }

    // ---- epilogue: stage tile, mix with x + rule, LN per l, write g_mixed ----
    asm volatile("cp.async.wait_group 0;");
    __syncthreads();
    float* S = sm;                // reuse: 64 x 260 fp32
    #pragma unroll
    for (int mt = 0; mt < 2; mt++) {
        int r0 = wm + mt * 16 + g;
        #pragma unroll
        for (int nt = 0; nt < 8; nt++) {
            int c = wn + nt * 8 + tg * 2;
            *(float2*)&S[r0 * XG_BW + c]       = make_float2(acc[mt][nt][0], acc[mt][nt][1]);
            *(float2*)&S[(r0 + 8) * XG_BW + c] = make_float2(acc[mt][nt][2], acc[mt][nt][3]);
        }
    }
    __syncthreads();

    int lg = t >> 4, part = t & 15;
    int l = lbase + lg;
    const float* xrow = x + ((size_t)b * L_ + l) * D_;
    float s1 = 0.f, s2 = 0.f;
    #pragma unroll 4
    for (int jj = 0; jj < 16; jj++) {
        int d = part * 64 + jj * 4;
        float4 xv = *(const float4*)(xrow + d);
        float4 rv = *(const float4*)(x + ((size_t)b * L_ + (d >> 5)) * D_ + l * 32 + (d & 31));
        const float* Sp = &S[(lg * 4 + (d >> 8)) * XG_BW + (d & 255)];
        float v0 = xv.x + 0.5f * rv.x + 0.5f * Sp[0];
        float v1 = xv.y + 0.5f * rv.y + 0.5f * Sp[1];
        float v2 = xv.z + 0.5f * rv.z + 0.5f * Sp[2];
        float v3 = xv.w + 0.5f * rv.w + 0.5f * Sp[3];
        s1 += v0 + v1 + v2 + v3;
        s2 += v0 * v0 + v1 * v1 + v2 * v2 + v3 * v3;
    }
    #pragma unroll
    for (int off = 8; off > 0; off >>= 1) {
        s1 += __shfl_xor_sync(0xffffffffu, s1, off);
        s2 += __shfl_xor_sync(0xffffffffu, s2, off);
    }
    if (part == 0) {
        float m = s1 * (1.f / 1024.f);
        float var = s2 * (1.f / 1024.f) - m * m;
        mmv[lg] = m; rrv[lg] = rsqrtf(var + 1e-5f);
    }
    __syncthreads();
    float m = mmv[lg], rs = rrv[lg];
    float* orow = g_mixed + ((size_t)b * L_ + l) * D_;
    #pragma unroll 4
    for (int jj = 0; jj < 16; jj++) {
        int d = part * 64 + jj * 4;
        float4 xv = *(const float4*)(xrow + d);
        float4 rv = *(const float4*)(x + ((size_t)b * L_ + (d >> 5)) * D_ + l * 32 + (d & 31));
        const float* Sp = &S[(lg * 4 + (d >> 8)) * XG_BW + (d & 255)];
        float4 gv = *(const float4*)(n1g + d);
        float4 bv = *(const float4*)(n1b + d);
        float4 o;
        o.x = (xv.x + 0.5f * rv.x + 0.5f * Sp[0] - m) * rs * gv.x + bv.x;
        o.y = (xv.y + 0.5f * rv.y + 0.5f * Sp[1] - m) * rs * gv.y + bv.y;
        o.z = (xv.z + 0.5f * rv.z + 0.5f * Sp[2] - m) * rs * gv.z + bv.z;
        o.w = (xv.w + 0.5f * rv.w + 0.5f * Sp[3] - m) * rs * gv.w + bv.w;
        *(float4*)(orow + d) = o;
    }
}

// ---------------- fused gate+up+silu GEMM -> g_H ----------------
__global__ __launch_bounds__(256, 2) void k_gu(const float* __restrict__ Wg,
                                               const float* __restrict__ Wu) {
    extern __shared__ float sm[];
    unsigned smem_u32 = (unsigned)__cvta_generic_to_shared(sm);

    int l    = blockIdx.x;
    int ntg0 = blockIdx.y * 64;
    int t    = threadIdx.x;

    const float* Ap  = g_mixed + (size_t)l * D_;
    const long  lda  = (long)L_ * D_;
    const float* Bg  = Wg + (size_t)l * D_ * DFF + ntg0;
    const float* Bu  = Wu + (size_t)l * D_ * DFF + ntg0;
    float* Op        = g_H + (size_t)l * DFF + ntg0;
    const int nit    = D_ / 32;

    int lane = t & 31, wid = t >> 5;
    int g = lane >> 2, tg = lane & 3;
    int wm = (wid & 1) * 32;
    int wn = (wid >> 1) * 16;

    float ag[2][2][4], au[2][2][4];
    #pragma unroll
    for (int mt = 0; mt < 2; mt++)
        #pragma unroll
        for (int nt = 0; nt < 2; nt++)
            #pragma unroll
            for (int e = 0; e < 4; e++) { ag[mt][nt][e] = 0.f; au[mt][nt][e] = 0.f; }

    auto issue = [&](int s) {
        if (s < nit) {
            int k0 = s * 32;
            unsigned base = smem_u32 + (s % STAGES) * STG_BYTES;
            #pragma unroll
            for (int i = 0; i < 2; i++) {
                int q = t + i * 256;
                int m = q >> 3, f4 = q & 7;
                unsigned dst = base + (unsigned)(m * STG_AW + f4 * 4) * 4u;
                const float* src = Ap + (size_t)m * lda + k0 + f4 * 4;
                asm volatile("cp.async.cg.shared.global [%0], [%1], 16;" :: "r"(dst), "l"(src));
            }
            #pragma unroll
            for (int i = 0; i < 2; i++) {
                int q = t + i * 256;
                int k = q >> 4, n4 = (q & 15) * 4;
                unsigned dstg = base + STG_AB + (unsigned)(k * STG_BW + n4) * 4u;
                unsigned dstu = base + STG_AB + (unsigned)(k * STG_BW + 64 + n4) * 4u;
                const float* sg = Bg + (size_t)(k0 + k) * DFF + n4;
                const float* su = Bu + (size_t)(k0 + k) * DFF + n4;
                asm volatile("cp.async.cg.shared.global [%0], [%1], 16;" :: "r"(dstg), "l"(sg));
                asm volatile("cp.async.cg.shared.global [%0], [%1], 16;" :: "r"(dstu), "l"(su));
            }
        }
        asm volatile("cp.async.commit_group;");
    };

    issue(0); issue(1); issue(2);

    for (int it = 0; it < nit; it++) {
        asm volatile("cp.async.wait_group 2;");
        __syncthreads();
        issue(it + 3);

        const float* Af = sm + (size_t)(it % STAGES) * (STG_BYTES / 4);
        const float* Bf = Af + STG_AB / 4;

        #pragma unroll
        for (int s = 0; s < 2; s++) {
            int kp0 = s * 8 + tg, kp1 = kp0 + 4;
            unsigned af[2][4];
            #pragma unroll
            for (int mt = 0; mt < 2; mt++) {
                int r0 = wm + mt * 16 + g, r1 = r0 + 8;
                float2 a00 = *(const float2*)&Af[r0 * STG_AW + 2 * kp0];
                float2 a10 = *(const float2*)&Af[r1 * STG_AW + 2 * kp0];
                float2 a01 = *(const float2*)&Af[r0 * STG_AW + 2 * kp1];
                float2 a11 = *(const float2*)&Af[r1 * STG_AW + 2 * kp1];
                af[mt][0] = pack16(a00.x, a00.y);
                af[mt][1] = pack16(a10.x, a10.y);
                af[mt][2] = pack16(a01.x, a01.y);
                af[mt][3] = pack16(a11.x, a11.y);
            }
            #pragma unroll
            for (int nt = 0; nt < 2; nt++) {
                int cn = wn + nt * 8 + g;
                unsigned bg0 = pack16(Bf[(2 * kp0) * STG_BW + cn], Bf[(2 * kp0 + 1) * STG_BW + cn]);
                unsigned bg1 = pack16(Bf[(2 * kp1) * STG_BW + cn], Bf[(2 * kp1 + 1) * STG_BW + cn]);
                unsigned bu0 = pack16(Bf[(2 * kp0) * STG_BW + 64 + cn], Bf[(2 * kp0 + 1) * STG_BW + 64 + cn]);
                unsigned bu1 = pack16(Bf[(2 * kp1) * STG_BW + 64 + cn], Bf[(2 * kp1 + 1) * STG_BW + 64 + cn]);
                mma16816(ag[0][nt], af[0], bg0, bg1);
                mma16816(ag[1][nt], af[1], bg0, bg1);
                mma16816(au[0][nt], af[0], bu0, bu1);
                mma16816(au[1][nt], af[1], bu0, bu1);
            }
        }
        __syncthreads();
    }

    const long ostride = (long)L_ * DFF;
    #pragma unroll
    for (int mt = 0; mt < 2; mt++) {
        int r0 = wm + mt * 16 + g;
        #pragma unroll
        for (int nt = 0; nt < 2; nt++) {
            int c = wn + nt * 8 + tg * 2;
            float h0 = ag[mt][nt][0] / (1.f + __expf(-ag[mt][nt][0])) * au[mt][nt][0];
            float h1 = ag[mt][nt][1] / (1.f + __expf(-ag[mt][nt][1])) * au[mt][nt][1];
            float h2 = ag[mt][nt][2] / (1.f + __expf(-ag[mt][nt][2])) * au[mt][nt][2];
            float h3 = ag[mt][nt][3] / (1.f + __expf(-ag[mt][nt][3])) * au[mt][nt][3];
            float* p0 = Op + (size_t)r0 * ostride + c;
            float* p1 = Op + (size_t)(r0 + 8) * ostride + c;
            *(float2*)p0 = make_float2(h0, h1);
            *(float2*)p1 = make_float2(h2, h3);
        }
    }
}

// ---------------- K8: out = LN(mixed+ffn, n2); y_out = y + ffn [prefetched] ----
__global__ void k_final(const float* __restrict__ y,
                        const float* __restrict__ n2g, const float* __restrict__ n2b,
                        float* __restrict__ out) {
    int row = blockIdx.x;
    int t = threadIdx.x;
    size_t base = (size_t)row * D_ + t * 4;
    float4 f4 = *(const float4*)(g_ffn + base);
    float4 m4 = *(const float4*)(g_mixed + base);
    float4 y4 = *(const float4*)(y + base);
    float v[4] = {m4.x + f4.x, m4.y + f4.y, m4.z + f4.z, m4.w + f4.w};
    float fv[4] = {f4.x, f4.y, f4.z, f4.w};
    float yv[4] = {y4.x, y4.y, y4.z, y4.w};
    float s1 = 0.f, s2 = 0.f;
    #pragma unroll
    for (int e = 0; e < 4; e++) { s1 += v[e]; s2 += v[e] * v[e]; }
    blockReduce2_256(s1, s2);
    float m = s1 * (1.f / D_);
    float var = s2 * (1.f / D_) - m * m;
    float rs = rsqrtf(var + 1e-5f);
    #pragma unroll
    for (int e = 0; e < 4; e++) {
        int d = t * 4 + e;
        out[base + e] = (v[e] - m) * rs * n2g[d] + n2b[d];
        out[(size_t)B_ * L_ * D_ + base + e] = yv[e] + fv[e];
    }
}

// ---------------- launch ----------------
extern "C" void kernel_launch(void* const* d_in, const int* in_sizes, int n_in,
                              void* d_out, int out_size) {
    const float* x       = (const float*)d_in[0];
    const float* y       = (const float*)d_in[1];
    const float* A_log   = (const float*)d_in[2];
    const float* W_1     = (const float*)d_in[3];
    const float* W_V     = (const float*)d_in[4];
    const float* kn1_g   = (const float*)d_in[5];
    const float* kn1_b   = (const float*)d_in[6];
    const float* kn2_g   = (const float*)d_in[7];
    const float* kn2_b   = (const float*)d_in[8];
    const float* W_gate  = (const float*)d_in[9];
    const float* W_up    = (const float*)d_in[10];
    const float* W_down  = (const float*)d_in[11];
    const float* ny_g    = (const float*)d_in[12];
    const float* ny_b    = (const float*)d_in[13];
    const float* n1_g    = (const float*)d_in[14];
    const float* n1_b    = (const float*)d_in[15];
    const float* n2_g    = (const float*)d_in[16];
    const float* n2_b    = (const float*)d_in[17];
    float* out = (float*)d_out;

    static int smem_set = 0;
    if (!smem_set) {
        cudaFuncSetAttribute(k_gemm,  cudaFuncAttributeMaxDynamicSharedMemorySize, GEMM_SMEM);
        cudaFuncSetAttribute(k_gu,    cudaFuncAttributeMaxDynamicSharedMemorySize, GEMM_SMEM);
        cudaFuncSetAttribute(k_xgmix, cudaFuncAttributeMaxDynamicSharedMemorySize, XG_SMEM);
        smem_set = 1;
    }

    k_prepA<<<N_, 256>>>(A_log);
    k_prepW1<<<dim3(16, 8), 128>>>(W_1, W_V);
    k_prepWinv<<<N_, 128>>>();
    k_xr<<<B_ * L_, 256>>>(x, y, ny_g, ny_b, kn1_g, kn1_b);
    k_gemm<<<dim3(N_, 1), 256, GEMM_SMEM>>>(nullptr, 3);           // x_local
    k_trln<<<dim3(4, B_), 256>>>(kn2_g, kn2_b);
    k_xgmix<<<128, 256, XG_SMEM>>>(x, n1_g, n1_b);                 // x_global + mix + LN
    k_gu<<<dim3(L_, DFF / 64), 256, GEMM_SMEM>>>(W_gate, W_up);    // gate+up+silu
    k_gemm<<<dim3(L_, D_ / 128), 256, GEMM_SMEM>>>(W_down, 1);     // down
    k_final<<<B_ * L_, 256>>>(y, n2_g, n2_b, out);
}

// round 11
// speedup vs baseline: 1.0566x; 1.0566x over previous
#include <cuda_runtime.h>
#include <cuda_fp16.h>
#include <math.h>

#define B_   64
#define L_   32
#define D_   1024
#define DFF  2048
#define K_   128
#define N_   256

// ---------------- scratch (no allocations allowed) ----------------
__device__ float g_A[N_ * N_];
__device__ float g_W[N_ * K_ * K_];      // UNNORMALIZED Wl
__device__ float g_winv[N_ * K_];
__device__ float g_wpart[8][N_ * K_];
__device__ float g_xr[B_ * N_ * K_];
__device__ float g_xloc[B_ * N_ * K_];
__device__ float g_xln[B_ * K_ * N_];
__device__ float g_xglob[B_ * K_ * N_];
__device__ float g_mixed[B_ * L_ * D_];
__device__ __half g_H[B_ * L_ * DFF];    // fp16 H = silu(gate)*up
__device__ float g_ffn[B_ * L_ * D_];

// ---------------- helpers ----------------
__device__ __forceinline__ void blockReduce2_256(float& s1, float& s2) {
    __shared__ float sh1[8], sh2[8];
    int t = threadIdx.x;
    #pragma unroll
    for (int o = 16; o > 0; o >>= 1) {
        s1 += __shfl_xor_sync(0xffffffffu, s1, o);
        s2 += __shfl_xor_sync(0xffffffffu, s2, o);
    }
    if ((t & 31) == 0) { sh1[t >> 5] = s1; sh2[t >> 5] = s2; }
    __syncthreads();
    float a = 0.f, b = 0.f;
    #pragma unroll
    for (int w = 0; w < 8; w++) { a += sh1[w]; b += sh2[w]; }
    s1 = a; s2 = b;
    __syncthreads();
}

__device__ __forceinline__ unsigned pack16(float x0, float x1) {
    unsigned h;
    asm("cvt.rn.f16x2.f32 %0, %1, %2;" : "=r"(h) : "f"(x1), "f"(x0));
    return h;
}

__device__ __forceinline__ void mma16816(float* c, const unsigned* a, unsigned b0, unsigned b1) {
    asm volatile(
        "mma.sync.aligned.m16n8k16.row.col.f32.f16.f16.f32 "
        "{%0,%1,%2,%3}, {%4,%5,%6,%7}, {%8,%9}, {%0,%1,%2,%3};"
        : "+f"(c[0]), "+f"(c[1]), "+f"(c[2]), "+f"(c[3])
        : "r"(a[0]), "r"(a[1]), "r"(a[2]), "r"(a[3]), "r"(b0), "r"(b1));
}

// ---------------- K0: A = A_logits / max(||col||, eps) ----------------
__global__ void k_prepA(const float* __restrict__ Al) {
    int j = blockIdx.x;
    int i = threadIdx.x;
    float v = Al[i * N_ + j];
    float s1 = v * v, s2 = 0.f;
    blockReduce2_256(s1, s2);
    float inv = 1.f / fmaxf(sqrtf(s1), 1e-12f);
    g_A[i * N_ + j] = v * inv;
}

// ---------------- prepW ----------------
__global__ void k_prepW1(const float* __restrict__ W1, const float* __restrict__ WV) {
    int tt = blockIdx.x;
    int is = blockIdx.y;
    int o  = threadIdx.x;
    __shared__ float w1s[16][8];
    w1s[o >> 3][o & 7] = W1[(tt * 16 + (o >> 3)) * 8 + (o & 7)];
    __syncthreads();
    float ss[16];
    #pragma unroll
    for (int tl = 0; tl < 16; tl++) ss[tl] = 0.f;
    for (int ii = 0; ii < 16; ii++) {
        int i = is * 16 + ii;
        float wv[8];
        #pragma unroll
        for (int k = 0; k < 8; k++) wv[k] = WV[((size_t)k * K_ + i) * K_ + o];
        #pragma unroll
        for (int tl = 0; tl < 16; tl++) {
            float wl = 0.f;
            #pragma unroll
            for (int k = 0; k < 8; k++) wl += w1s[tl][k] * wv[k];
            ss[tl] += wl * wl;
            g_W[((size_t)(tt * 16 + tl) * K_ + i) * K_ + o] = wl;
        }
    }
    #pragma unroll
    for (int tl = 0; tl < 16; tl++)
        g_wpart[is][(tt * 16 + tl) * K_ + o] = ss[tl];
}

__global__ void k_prepWinv() {
    int t = blockIdx.x;
    int o = threadIdx.x;
    float ss = 0.f;
    #pragma unroll
    for (int s = 0; s < 8; s++) ss += g_wpart[s][t * K_ + o];
    g_winv[t * K_ + o] = 1.f / fmaxf(sqrtf(ss), 1e-12f);
}

// ---------------- K2: xr = LN128( x + LN_D(y) )  [prefetched] ----------------
__global__ void k_xr(const float* __restrict__ x, const float* __restrict__ y,
                     const float* __restrict__ nyg, const float* __restrict__ nyb,
                     const float* __restrict__ kn1g, const float* __restrict__ kn1b) {
    int row = blockIdx.x;
    int t = threadIdx.x;
    float4 yv4 = *(const float4*)(y + (size_t)row * D_ + t * 4);
    float4 xv4 = *(const float4*)(x + (size_t)row * D_ + t * 4);
    float yv[4] = {yv4.x, yv4.y, yv4.z, yv4.w};
    float xv[4] = {xv4.x, xv4.y, xv4.z, xv4.w};
    float s1 = 0.f, s2 = 0.f;
    #pragma unroll
    for (int e = 0; e < 4; e++) { s1 += yv[e]; s2 += yv[e] * yv[e]; }
    blockReduce2_256(s1, s2);
    float m = s1 * (1.f / D_);
    float var = s2 * (1.f / D_) - m * m;
    float rs = rsqrtf(var + 1e-5f);
    float kin[4];
    float ls1 = 0.f, ls2 = 0.f;
    #pragma unroll
    for (int e = 0; e < 4; e++) {
        int d = t * 4 + e;
        float ny = (yv[e] - m) * rs * nyg[d] + nyb[d];
        float kv = xv[e] + ny;
        kin[e] = kv; ls1 += kv; ls2 += kv * kv;
    }
    #pragma unroll
    for (int o = 16; o > 0; o >>= 1) {
        ls1 += __shfl_xor_sync(0xffffffffu, ls1, o);
        ls2 += __shfl_xor_sync(0xffffffffu, ls2, o);
    }
    float lm = ls1 * (1.f / 128.f);
    float lv = ls2 * (1.f / 128.f) - lm * lm;
    float lrs = rsqrtf(lv + 1e-5f);
    #pragma unroll
    for (int e = 0; e < 4; e++) {
        int d = t * 4 + e;
        int i = d & 127;
        g_xr[(size_t)row * D_ + d] = (kin[e] - lm) * lrs * kn1g[i] + kn1b[i];
    }
}

// ---------------- K4a: transpose + LN over N (kn2) ----------------
__global__ void k_trln(const float* __restrict__ kn2g, const float* __restrict__ kn2b) {
    int k0 = blockIdx.x * 32;
    int b  = blockIdx.y;
    int t  = threadIdx.x;
    __shared__ float tr[32][264];
    __shared__ float mm[32], rr[32];
    for (int q = t; q < 2048; q += 256) {
        int n = q >> 3, f = q & 7;
        float4 v = *(const float4*)&g_xloc[((size_t)b * N_ + n) * K_ + k0 + f * 4];
        tr[f * 4 + 0][n] = v.x; tr[f * 4 + 1][n] = v.y;
        tr[f * 4 + 2][n] = v.z; tr[f * 4 + 3][n] = v.w;
    }
    __syncthreads();
    int k = t >> 3, s = t & 7;
    float s1 = 0.f, s2 = 0.f;
    #pragma unroll 8
    for (int j = 0; j < 32; j++) {
        float v = tr[k][s + 8 * j];
        s1 += v; s2 += v * v;
    }
    #pragma unroll
    for (int off = 4; off > 0; off >>= 1) {
        s1 += __shfl_xor_sync(0xffffffffu, s1, off);
        s2 += __shfl_xor_sync(0xffffffffu, s2, off);
    }
    if (s == 0) {
        float m = s1 * (1.f / N_);
        float var = s2 * (1.f / N_) - m * m;
        mm[k] = m; rr[k] = rsqrtf(var + 1e-5f);
    }
    __syncthreads();
    int n2 = t;
    float gn = kn2g[n2], bn = kn2b[n2];
    #pragma unroll 4
    for (int kk = 0; kk < 32; kk++) {
        float v = (tr[kk][n2] - mm[kk]) * rr[kk] * gn + bn;
        g_xln[((size_t)b * K_ + k0 + kk) * N_ + n2] = v;
    }
}

// ---------------- K5: mixed = LN( x + 0.5*rule + 0.5*kron , n1) ----------------
__global__ void k_mixed(const float* __restrict__ x,
                        const float* __restrict__ n1g, const float* __restrict__ n1b) {
    int row = blockIdx.x;
    int b = row >> 5, l = row & 31;
    int t = threadIdx.x;
    float v[4];
    float s1 = 0.f, s2 = 0.f;
    #pragma unroll
    for (int e = 0; e < 4; e++) {
        int d = t * 4 + e;
        float rule = x[((size_t)b * L_ + (d >> 5)) * D_ + l * 32 + (d & 31)];
        float kron = g_xglob[(size_t)row * D_ + d];
        float xv   = x[(size_t)row * D_ + d];
        float val = xv + 0.5f * rule + 0.5f * kron;
        v[e] = val; s1 += val; s2 += val * val;
    }
    blockReduce2_256(s1, s2);
    float m = s1 * (1.f / D_);
    float var = s2 * (1.f / D_) - m * m;
    float rs = rsqrtf(var + 1e-5f);
    #pragma unroll
    for (int e = 0; e < 4; e++) {
        int d = t * 4 + e;
        g_mixed[(size_t)row * D_ + d] = (v[e] - m) * rs * n1g[d] + n1b[d];
    }
}

// ---------------- generic cp.async pipelined fp16 tensor-core GEMM (fp32 A) ------
// mode 2: xglob A=g_xln rows [64x256] @ g_A [256x128tile] -> g_xglob
// mode 3: xloc  A=g_xr(:,n,:) [64x128] @ g_W(n)[128x128], scale g_winv(n) -> g_xloc
#define STAGES   4
#define STG_AW   40
#define STG_BW   132
#define STG_AB   10240
#define STG_BYTES 27136
#define GEMM_SMEM (STAGES * STG_BYTES)

__global__ __launch_bounds__(256, 2) void k_gemm(int mode) {
    extern __shared__ float sm[];
    unsigned smem_u32 = (unsigned)__cvta_generic_to_shared(sm);

    int bx  = blockIdx.x;
    int nt0 = blockIdx.y * 128;
    int t   = threadIdx.x;

    const float* Ap; long lda, ostride; int Kdim, width;
    const float* Bp; float* Op; const float* sc = 0;
    if (mode == 2) {
        Ap = g_xln + (size_t)bx * 64 * N_; lda = N_; Kdim = N_; width = N_;
        Bp = g_A + nt0;
        Op = g_xglob + (size_t)bx * 64 * N_ + nt0;
        ostride = N_;
    } else {
        Ap = g_xr + (size_t)bx * K_; lda = (long)N_ * K_; Kdim = K_; width = K_;
        Bp = g_W + (size_t)bx * K_ * K_;
        Op = g_xloc + (size_t)bx * K_;
        ostride = (long)N_ * K_;
        sc = g_winv + (size_t)bx * K_;
    }
    int nit = Kdim / 32;

    int lane = t & 31, wid = t >> 5;
    int g = lane >> 2, tg = lane & 3;
    int wm = (wid & 1) * 32;
    int wn = (wid >> 1) * 32;

    float acc[2][4][4];
    #pragma unroll
    for (int mt = 0; mt < 2; mt++)
        #pragma unroll
        for (int nt = 0; nt < 4; nt++)
            #pragma unroll
            for (int e = 0; e < 4; e++) acc[mt][nt][e] = 0.f;

    auto issue = [&](int s) {
        if (s < nit) {
            int k0 = s * 32;
            unsigned base = smem_u32 + (s % STAGES) * STG_BYTES;
            #pragma unroll
            for (int i = 0; i < 2; i++) {
                int q = t + i * 256;
                int m = q >> 3, f4 = q & 7;
                unsigned dst = base + (unsigned)(m * STG_AW + f4 * 4) * 4u;
                const float* src = Ap + (size_t)m * lda + k0 + f4 * 4;
                asm volatile("cp.async.cg.shared.global [%0], [%1], 16;" :: "r"(dst), "l"(src));
            }
            #pragma unroll
            for (int i = 0; i < 4; i++) {
                int q = t + i * 256;
                int k = q >> 5, n4 = (q & 31) * 4;
                unsigned dst = base + STG_AB + (unsigned)(k * STG_BW + n4) * 4u;
                const float* src = Bp + (size_t)(k0 + k) * width + n4;
                asm volatile("cp.async.cg.shared.global [%0], [%1], 16;" :: "r"(dst), "l"(src));
            }
        }
        asm volatile("cp.async.commit_group;");
    };

    issue(0); issue(1); issue(2);

    for (int it = 0; it < nit; it++) {
        asm volatile("cp.async.wait_group 2;");
        __syncthreads();
        issue(it + 3);

        const float* Af = sm + (size_t)(it % STAGES) * (STG_BYTES / 4);
        const float* Bf = Af + STG_AB / 4;

        #pragma unroll
        for (int s = 0; s < 2; s++) {
            int kp0 = s * 8 + tg, kp1 = kp0 + 4;
            unsigned af[2][4];
            #pragma unroll
            for (int mt = 0; mt < 2; mt++) {
                int r0 = wm + mt * 16 + g, r1 = r0 + 8;
                float2 a00 = *(const float2*)&Af[r0 * STG_AW + 2 * kp0];
                float2 a10 = *(const float2*)&Af[r1 * STG_AW + 2 * kp0];
                float2 a01 = *(const float2*)&Af[r0 * STG_AW + 2 * kp1];
                float2 a11 = *(const float2*)&Af[r1 * STG_AW + 2 * kp1];
                af[mt][0] = pack16(a00.x, a00.y);
                af[mt][1] = pack16(a10.x, a10.y);
                af[mt][2] = pack16(a01.x, a01.y);
                af[mt][3] = pack16(a11.x, a11.y);
            }
            #pragma unroll
            for (int nt = 0; nt < 4; nt++) {
                int cn = wn + nt * 8 + g;
                unsigned b0 = pack16(Bf[(2 * kp0) * STG_BW + cn], Bf[(2 * kp0 + 1) * STG_BW + cn]);
                unsigned b1 = pack16(Bf[(2 * kp1) * STG_BW + cn], Bf[(2 * kp1 + 1) * STG_BW + cn]);
                mma16816(acc[0][nt], af[0], b0, b1);
                mma16816(acc[1][nt], af[1], b0, b1);
            }
        }
        __syncthreads();
    }

    #pragma unroll
    for (int mt = 0; mt < 2; mt++) {
        int r0 = wm + mt * 16 + g;
        #pragma unroll
        for (int nt = 0; nt < 4; nt++) {
            int c = wn + nt * 8 + tg * 2;
            float v0 = acc[mt][nt][0], v1 = acc[mt][nt][1];
            float v2 = acc[mt][nt][2], v3 = acc[mt][nt][3];
            if (sc) {
                float s0 = sc[c], s1v = sc[c + 1];
                v0 *= s0; v1 *= s1v; v2 *= s0; v3 *= s1v;
            }
            float* p0 = Op + (size_t)r0 * ostride + c;
            float* p1 = Op + (size_t)(r0 + 8) * ostride + c;
            *(float2*)p0 = make_float2(v0, v1);
            *(float2*)p1 = make_float2(v2, v3);
        }
    }
}

// ---------------- fused gate+up+silu GEMM -> g_H (fp16) ----------------
__global__ __launch_bounds__(256, 2) void k_gu(const float* __restrict__ Wg,
                                               const float* __restrict__ Wu) {
    extern __shared__ float sm[];
    unsigned smem_u32 = (unsigned)__cvta_generic_to_shared(sm);

    int l    = blockIdx.x;
    int ntg0 = blockIdx.y * 64;
    int t    = threadIdx.x;

    const float* Ap  = g_mixed + (size_t)l * D_;
    const long  lda  = (long)L_ * D_;
    const float* Bg  = Wg + (size_t)l * D_ * DFF + ntg0;
    const float* Bu  = Wu + (size_t)l * D_ * DFF + ntg0;
    __half* Op       = g_H + (size_t)l * DFF + ntg0;
    const int nit    = D_ / 32;

    int lane = t & 31, wid = t >> 5;
    int g = lane >> 2, tg = lane & 3;
    int wm = (wid & 1) * 32;
    int wn = (wid >> 1) * 16;

    float ag[2][2][4], au[2][2][4];
    #pragma unroll
    for (int mt = 0; mt < 2; mt++)
        #pragma unroll
        for (int nt = 0; nt < 2; nt++)
            #pragma unroll
            for (int e = 0; e < 4; e++) { ag[mt][nt][e] = 0.f; au[mt][nt][e] = 0.f; }

    auto issue = [&](int s) {
        if (s < nit) {
            int k0 = s * 32;
            unsigned base = smem_u32 + (s % STAGES) * STG_BYTES;
            #pragma unroll
            for (int i = 0; i < 2; i++) {
                int q = t + i * 256;
                int m = q >> 3, f4 = q & 7;
                unsigned dst = base + (unsigned)(m * STG_AW + f4 * 4) * 4u;
                const float* src = Ap + (size_t)m * lda + k0 + f4 * 4;
                asm volatile("cp.async.cg.shared.global [%0], [%1], 16;" :: "r"(dst), "l"(src));
            }
            #pragma unroll
            for (int i = 0; i < 2; i++) {
                int q = t + i * 256;
                int k = q >> 4, n4 = (q & 15) * 4;
                unsigned dstg = base + STG_AB + (unsigned)(k * STG_BW + n4) * 4u;
                unsigned dstu = base + STG_AB + (unsigned)(k * STG_BW + 64 + n4) * 4u;
                const float* sg = Bg + (size_t)(k0 + k) * DFF + n4;
                const float* su = Bu + (size_t)(k0 + k) * DFF + n4;
                asm volatile("cp.async.cg.shared.global [%0], [%1], 16;" :: "r"(dstg), "l"(sg));
                asm volatile("cp.async.cg.shared.global [%0], [%1], 16;" :: "r"(dstu), "l"(su));
            }
        }
        asm volatile("cp.async.commit_group;");
    };

    issue(0); issue(1); issue(2);

    for (int it = 0; it < nit; it++) {
        asm volatile("cp.async.wait_group 2;");
        __syncthreads();
        issue(it + 3);

        const float* Af = sm + (size_t)(it % STAGES) * (STG_BYTES / 4);
        const float* Bf = Af + STG_AB / 4;

        #pragma unroll
        for (int s = 0; s < 2; s++) {
            int kp0 = s * 8 + tg, kp1 = kp0 + 4;
            unsigned af[2][4];
            #pragma unroll
            for (int mt = 0; mt < 2; mt++) {
                int r0 = wm + mt * 16 + g, r1 = r0 + 8;
                float2 a00 = *(const float2*)&Af[r0 * STG_AW + 2 * kp0];
                float2 a10 = *(const float2*)&Af[r1 * STG_AW + 2 * kp0];
                float2 a01 = *(const float2*)&Af[r0 * STG_AW + 2 * kp1];
                float2 a11 = *(const float2*)&Af[r1 * STG_AW + 2 * kp1];
                af[mt][0] = pack16(a00.x, a00.y);
                af[mt][1] = pack16(a10.x, a10.y);
                af[mt][2] = pack16(a01.x, a01.y);
                af[mt][3] = pack16(a11.x, a11.y);
            }
            #pragma unroll
            for (int nt = 0; nt < 2; nt++) {
                int cn = wn + nt * 8 + g;
                unsigned bg0 = pack16(Bf[(2 * kp0) * STG_BW + cn], Bf[(2 * kp0 + 1) * STG_BW + cn]);
                unsigned bg1 = pack16(Bf[(2 * kp1) * STG_BW + cn], Bf[(2 * kp1 + 1) * STG_BW + cn]);
                unsigned bu0 = pack16(Bf[(2 * kp0) * STG_BW + 64 + cn], Bf[(2 * kp0 + 1) * STG_BW + 64 + cn]);
                unsigned bu1 = pack16(Bf[(2 * kp1) * STG_BW + 64 + cn], Bf[(2 * kp1 + 1) * STG_BW + 64 + cn]);
                mma16816(ag[0][nt], af[0], bg0, bg1);
                mma16816(ag[1][nt], af[1], bg0, bg1);
                mma16816(au[0][nt], af[0], bu0, bu1);
                mma16816(au[1][nt], af[1], bu0, bu1);
            }
        }
        __syncthreads();
    }

    const long ostride = (long)L_ * DFF;
    #pragma unroll
    for (int mt = 0; mt < 2; mt++) {
        int r0 = wm + mt * 16 + g;
        #pragma unroll
        for (int nt = 0; nt < 2; nt++) {
            int c = wn + nt * 8 + tg * 2;
            float h0 = ag[mt][nt][0] / (1.f + __expf(-ag[mt][nt][0])) * au[mt][nt][0];
            float h1 = ag[mt][nt][1] / (1.f + __expf(-ag[mt][nt][1])) * au[mt][nt][1];
            float h2 = ag[mt][nt][2] / (1.f + __expf(-ag[mt][nt][2])) * au[mt][nt][2];
            float h3 = ag[mt][nt][3] / (1.f + __expf(-ag[mt][nt][3])) * au[mt][nt][3];
            *(__half2*)(Op + (size_t)r0 * ostride + c)       = __floats2half2_rn(h0, h1);
            *(__half2*)(Op + (size_t)(r0 + 8) * ostride + c) = __floats2half2_rn(h2, h3);
        }
    }
}

// ---------------- down GEMM: A = g_H fp16 [64x2048] @ W_down fp32 -> g_ffn ------
// A stage: 64 rows x 32 halfs, row stride 20 u32 (bank-conflict-free fragments)
#define DN_AW   20
#define DN_AB   5120
#define DN_STG  (DN_AB + 16896)     // 22016
#define DN_SMEM (STAGES * DN_STG)   // 88064

__global__ __launch_bounds__(256, 2) void k_dn(const float* __restrict__ Wd) {
    extern __shared__ float sm[];
    unsigned smem_u32 = (unsigned)__cvta_generic_to_shared(sm);

    int l   = blockIdx.x;
    int nt0 = blockIdx.y * 128;
    int t   = threadIdx.x;

    const __half* Ap = g_H + (size_t)l * DFF;
    const long  lda  = (long)L_ * DFF;       // in halfs
    const float* Bp  = Wd + (size_t)l * DFF * D_ + nt0;
    float* Op        = g_ffn + (size_t)l * D_ + nt0;
    const int nit    = DFF / 32;             // 64

    int lane = t & 31, wid = t >> 5;
    int g = lane >> 2, tg = lane & 3;
    int wm = (wid & 1) * 32;
    int wn = (wid >> 1) * 32;

    float acc[2][4][4];
    #pragma unroll
    for (int mt = 0; mt < 2; mt++)
        #pragma unroll
        for (int nt = 0; nt < 4; nt++)
            #pragma unroll
            for (int e = 0; e < 4; e++) acc[mt][nt][e] = 0.f;

    auto issue = [&](int s) {
        if (s < nit) {
            int k0 = s * 32;
            unsigned base = smem_u32 + (s % STAGES) * DN_STG;
            // A fp16: 64 rows x 64B; 1 transfer per thread
            {
                int m = t >> 2, seg = t & 3;
                unsigned dst = base + (unsigned)(m * DN_AW * 4 + seg * 16);
                const __half* src = Ap + (size_t)m * lda + k0 + seg * 8;
                asm volatile("cp.async.cg.shared.global [%0], [%1], 16;" :: "r"(dst), "l"(src));
            }
            // B fp32: 32 x 128
            #pragma unroll
            for (int i = 0; i < 4; i++) {
                int q = t + i * 256;
                int k = q >> 5, n4 = (q & 31) * 4;
                unsigned dst = base + DN_AB + (unsigned)(k * STG_BW + n4) * 4u;
                const float* src = Bp + (size_t)(k0 + k) * D_ + n4;
                asm volatile("cp.async.cg.shared.global [%0], [%1], 16;" :: "r"(dst), "l"(src));
            }
        }
        asm volatile("cp.async.commit_group;");
    };

    issue(0); issue(1); issue(2);

    for (int it = 0; it < nit; it++) {
        asm volatile("cp.async.wait_group 2;");
        __syncthreads();
        issue(it + 3);

        const unsigned* Au = (const unsigned*)(sm + (size_t)(it % STAGES) * (DN_STG / 4));
        const float* Bf = sm + (size_t)(it % STAGES) * (DN_STG / 4) + DN_AB / 4;

        #pragma unroll
        for (int s = 0; s < 2; s++) {
            int kp0 = s * 8 + tg, kp1 = kp0 + 4;
            unsigned af[2][4];
            #pragma unroll
            for (int mt = 0; mt < 2; mt++) {
                int r0 = wm + mt * 16 + g, r1 = r0 + 8;
                af[mt][0] = Au[r0 * DN_AW + kp0];
                af[mt][1] = Au[r1 * DN_AW + kp0];
                af[mt][2] = Au[r0 * DN_AW + kp1];
                af[mt][3] = Au[r1 * DN_AW + kp1];
            }
            #pragma unroll
            for (int nt = 0; nt < 4; nt++) {
                int cn = wn + nt * 8 + g;
                unsigned b0 = pack16(Bf[(2 * kp0) * STG_BW + cn], Bf[(2 * kp0 + 1) * STG_BW + cn]);
                unsigned b1 = pack16(Bf[(2 * kp1) * STG_BW + cn], Bf[(2 * kp1 + 1) * STG_BW + cn]);
                mma16816(acc[0][nt], af[0], b0, b1);
                mma16816(acc[1][nt], af[1], b0, b1);
            }
        }
        __syncthreads();
    }

    const long ostride = (long)L_ * D_;
    #pragma unroll
    for (int mt = 0; mt < 2; mt++) {
        int r0 = wm + mt * 16 + g;
        #pragma unroll
        for (int nt = 0; nt < 4; nt++) {
            int c = wn + nt * 8 + tg * 2;
            float* p0 = Op + (size_t)r0 * ostride + c;
            float* p1 = Op + (size_t)(r0 + 8) * ostride + c;
            *(float2*)p0 = make_float2(acc[mt][nt][0], acc[mt][nt][1]);
            *(float2*)p1 = make_float2(acc[mt][nt][2], acc[mt][nt][3]);
        }
    }
}

// ---------------- K8: out = LN(mixed+ffn, n2); y_out = y + ffn [prefetched] ----
__global__ void k_final(const float* __restrict__ y,
                        const float* __restrict__ n2g, const float* __restrict__ n2b,
                        float* __restrict__ out) {
    int row = blockIdx.x;
    int t = threadIdx.x;
    size_t base = (size_t)row * D_ + t * 4;
    float4 f4 = *(const float4*)(g_ffn + base);
    float4 m4 = *(const float4*)(g_mixed + base);
    float4 y4 = *(const float4*)(y + base);
    float v[4] = {m4.x + f4.x, m4.y + f4.y, m4.z + f4.z, m4.w + f4.w};
    float fv[4] = {f4.x, f4.y, f4.z, f4.w};
    float yv[4] = {y4.x, y4.y, y4.z, y4.w};
    float s1 = 0.f, s2 = 0.f;
    #pragma unroll
    for (int e = 0; e < 4; e++) { s1 += v[e]; s2 += v[e] * v[e]; }
    blockReduce2_256(s1, s2);
    float m = s1 * (1.f / D_);
    float var = s2 * (1.f / D_) - m * m;
    float rs = rsqrtf(var + 1e-5f);
    #pragma unroll
    for (int e = 0; e < 4; e++) {
        int d = t * 4 + e;
        out[base + e] = (v[e] - m) * rs * n2g[d] + n2b[d];
        out[(size_t)B_ * L_ * D_ + base + e] = yv[e] + fv[e];
    }
}

// ---------------- launch ----------------
extern "C" void kernel_launch(void* const* d_in, const int* in_sizes, int n_in,
                              void* d_out, int out_size) {
    const float* x       = (const float*)d_in[0];
    const float* y       = (const float*)d_in[1];
    const float* A_log   = (const float*)d_in[2];
    const float* W_1     = (const float*)d_in[3];
    const float* W_V     = (const float*)d_in[4];
    const float* kn1_g   = (const float*)d_in[5];
    const float* kn1_b   = (const float*)d_in[6];
    const float* kn2_g   = (const float*)d_in[7];
    const float* kn2_b   = (const float*)d_in[8];
    const float* W_gate  = (const float*)d_in[9];
    const float* W_up    = (const float*)d_in[10];
    const float* W_down  = (const float*)d_in[11];
    const float* ny_g    = (const float*)d_in[12];
    const float* ny_b    = (const float*)d_in[13];
    const float* n1_g    = (const float*)d_in[14];
    const float* n1_b    = (const float*)d_in[15];
    const float* n2_g    = (const float*)d_in[16];
    const float* n2_b    = (const float*)d_in[17];
    float* out = (float*)d_out;

    static int smem_set = 0;
    if (!smem_set) {
        cudaFuncSetAttribute(k_gemm, cudaFuncAttributeMaxDynamicSharedMemorySize, GEMM_SMEM);
        cudaFuncSetAttribute(k_gu,   cudaFuncAttributeMaxDynamicSharedMemorySize, GEMM_SMEM);
        cudaFuncSetAttribute(k_dn,   cudaFuncAttributeMaxDynamicSharedMemorySize, DN_SMEM);
        smem_set = 1;
    }

    k_prepA<<<N_, 256>>>(A_log);
    k_prepW1<<<dim3(16, 8), 128>>>(W_1, W_V);
    k_prepWinv<<<N_, 128>>>();
    k_xr<<<B_ * L_, 256>>>(x, y, ny_g, ny_b, kn1_g, kn1_b);
    k_gemm<<<dim3(N_, 1), 256, GEMM_SMEM>>>(3);                    // x_local
    k_trln<<<dim3(4, B_), 256>>>(kn2_g, kn2_b);
    k_gemm<<<dim3(128, 2), 256, GEMM_SMEM>>>(2);                   // x_global
    k_mixed<<<B_ * L_, 256>>>(x, n1_g, n1_b);
    k_gu<<<dim3(L_, DFF / 64), 256, GEMM_SMEM>>>(W_gate, W_up);    // gate+up+silu -> fp16 H
    k_dn<<<dim3(L_, D_ / 128), 256, DN_SMEM>>>(W_down);            // down
    k_final<<<B_ * L_, 256>>>(y, n2_g, n2_b, out);
}

// round 13
// speedup vs baseline: 1.0640x; 1.0070x over previous
#include <cuda_runtime.h>
#include <cuda_fp16.h>
#include <math.h>

#define B_   64
#define L_   32
#define D_   1024
#define DFF  2048
#define K_   128
#define N_   256

// ---------------- scratch (no allocations allowed) ----------------
__device__ float g_A[N_ * N_];
__device__ float g_W[N_ * K_ * K_];      // UNNORMALIZED Wl
__device__ float g_wpart[8][N_ * K_];
__device__ float g_xr[B_ * N_ * K_];
__device__ float g_xloc[B_ * N_ * K_];
__device__ float g_xln[B_ * K_ * N_];
__device__ float g_xglob[B_ * K_ * N_];
__device__ float g_mixed[B_ * L_ * D_];
__device__ __half g_H[B_ * L_ * DFF];    // fp16 H = silu(gate)*up
__device__ float g_ffn[B_ * L_ * D_];

// ---------------- helpers ----------------
__device__ __forceinline__ void blockReduce2_256(float& s1, float& s2) {
    __shared__ float sh1[8], sh2[8];
    int t = threadIdx.x;
    #pragma unroll
    for (int o = 16; o > 0; o >>= 1) {
        s1 += __shfl_xor_sync(0xffffffffu, s1, o);
        s2 += __shfl_xor_sync(0xffffffffu, s2, o);
    }
    if ((t & 31) == 0) { sh1[t >> 5] = s1; sh2[t >> 5] = s2; }
    __syncthreads();
    float a = 0.f, b = 0.f;
    #pragma unroll
    for (int w = 0; w < 8; w++) { a += sh1[w]; b += sh2[w]; }
    s1 = a; s2 = b;
    __syncthreads();
}

__device__ __forceinline__ unsigned pack16(float x0, float x1) {
    unsigned h;
    asm("cvt.rn.f16x2.f32 %0, %1, %2;" : "=r"(h) : "f"(x1), "f"(x0));
    return h;
}

__device__ __forceinline__ void mma16816(float* c, const unsigned* a, unsigned b0, unsigned b1) {
    asm volatile(
        "mma.sync.aligned.m16n8k16.row.col.f32.f16.f16.f32 "
        "{%0,%1,%2,%3}, {%4,%5,%6,%7}, {%8,%9}, {%0,%1,%2,%3};"
        : "+f"(c[0]), "+f"(c[1]), "+f"(c[2]), "+f"(c[3])
        : "r"(a[0]), "r"(a[1]), "r"(a[2]), "r"(a[3]), "r"(b0), "r"(b1));
}

// ---------------- K_pre: fused xr (2048 blocks) + prepA (256) + prepW1 (128) ----
__global__ void k_pre(const float* __restrict__ x, const float* __restrict__ y,
                      const float* __restrict__ nyg, const float* __restrict__ nyb,
                      const float* __restrict__ kn1g, const float* __restrict__ kn1b,
                      const float* __restrict__ Al,
                      const float* __restrict__ W1, const float* __restrict__ WV) {
    int bx = blockIdx.x;
    int t = threadIdx.x;

    if (bx < 2048) {
        // ---- xr = LN128( x + LN_D(y) )
        int row = bx;
        float4 yv4 = *(const float4*)(y + (size_t)row * D_ + t * 4);
        float4 xv4 = *(const float4*)(x + (size_t)row * D_ + t * 4);
        float yv[4] = {yv4.x, yv4.y, yv4.z, yv4.w};
        float xv[4] = {xv4.x, xv4.y, xv4.z, xv4.w};
        float s1 = 0.f, s2 = 0.f;
        #pragma unroll
        for (int e = 0; e < 4; e++) { s1 += yv[e]; s2 += yv[e] * yv[e]; }
        blockReduce2_256(s1, s2);
        float m = s1 * (1.f / D_);
        float var = s2 * (1.f / D_) - m * m;
        float rs = rsqrtf(var + 1e-5f);
        float kin[4];
        float ls1 = 0.f, ls2 = 0.f;
        #pragma unroll
        for (int e = 0; e < 4; e++) {
            int d = t * 4 + e;
            float ny = (yv[e] - m) * rs * nyg[d] + nyb[d];
            float kv = xv[e] + ny;
            kin[e] = kv; ls1 += kv; ls2 += kv * kv;
        }
        #pragma unroll
        for (int o = 16; o > 0; o >>= 1) {
            ls1 += __shfl_xor_sync(0xffffffffu, ls1, o);
            ls2 += __shfl_xor_sync(0xffffffffu, ls2, o);
        }
        float lm = ls1 * (1.f / 128.f);
        float lv = ls2 * (1.f / 128.f) - lm * lm;
        float lrs = rsqrtf(lv + 1e-5f);
        #pragma unroll
        for (int e = 0; e < 4; e++) {
            int d = t * 4 + e;
            int i = d & 127;
            g_xr[(size_t)row * D_ + d] = (kin[e] - lm) * lrs * kn1g[i] + kn1b[i];
        }
    } else if (bx < 2048 + 256) {
        // ---- prepA: A = A_logits / max(||col||, eps)
        int j = bx - 2048;
        float v = Al[t * N_ + j];
        float s1 = v * v, s2 = 0.f;
        blockReduce2_256(s1, s2);
        float inv = 1.f / fmaxf(sqrtf(s1), 1e-12f);
        g_A[t * N_ + j] = v * inv;
    } else {
        // ---- prepW1: unnormalized Wl + partial sumsq (128 threads active)
        int bb = bx - 2048 - 256;          // 0..127
        int tt = bb >> 3, is = bb & 7;
        __shared__ float w1s[16][8];
        if (t < 128) w1s[t >> 3][t & 7] = W1[(tt * 16 + (t >> 3)) * 8 + (t & 7)];
        __syncthreads();
        if (t < 128) {
            int o = t;
            float ss[16];
            #pragma unroll
            for (int tl = 0; tl < 16; tl++) ss[tl] = 0.f;
            for (int ii = 0; ii < 16; ii++) {
                int i = is * 16 + ii;
                float wv[8];
                #pragma unroll
                for (int k = 0; k < 8; k++) wv[k] = WV[((size_t)k * K_ + i) * K_ + o];
                #pragma unroll
                for (int tl = 0; tl < 16; tl++) {
                    float wl = 0.f;
                    #pragma unroll
                    for (int k = 0; k < 8; k++) wl += w1s[tl][k] * wv[k];
                    ss[tl] += wl * wl;
                    g_W[((size_t)(tt * 16 + tl) * K_ + i) * K_ + o] = wl;
                }
            }
            #pragma unroll
            for (int tl = 0; tl < 16; tl++)
                g_wpart[is][(tt * 16 + tl) * K_ + o] = ss[tl];
        }
    }
}

// ---------------- K4a: transpose + LN over N (kn2) ----------------
__global__ void k_trln(const float* __restrict__ kn2g, const float* __restrict__ kn2b) {
    int k0 = blockIdx.x * 32;
    int b  = blockIdx.y;
    int t  = threadIdx.x;
    __shared__ float tr[32][264];
    __shared__ float mm[32], rr[32];
    for (int q = t; q < 2048; q += 256) {
        int n = q >> 3, f = q & 7;
        float4 v = *(const float4*)&g_xloc[((size_t)b * N_ + n) * K_ + k0 + f * 4];
        tr[f * 4 + 0][n] = v.x; tr[f * 4 + 1][n] = v.y;
        tr[f * 4 + 2][n] = v.z; tr[f * 4 + 3][n] = v.w;
    }
    __syncthreads();
    int k = t >> 3, s = t & 7;
    float s1 = 0.f, s2 = 0.f;
    #pragma unroll 8
    for (int j = 0; j < 32; j++) {
        float v = tr[k][s + 8 * j];
        s1 += v; s2 += v * v;
    }
    #pragma unroll
    for (int off = 4; off > 0; off >>= 1) {
        s1 += __shfl_xor_sync(0xffffffffu, s1, off);
        s2 += __shfl_xor_sync(0xffffffffu, s2, off);
    }
    if (s == 0) {
        float m = s1 * (1.f / N_);
        float var = s2 * (1.f / N_) - m * m;
        mm[k] = m; rr[k] = rsqrtf(var + 1e-5f);
    }
    __syncthreads();
    int n2 = t;
    float gn = kn2g[n2], bn = kn2b[n2];
    #pragma unroll 4
    for (int kk = 0; kk < 32; kk++) {
        float v = (tr[kk][n2] - mm[kk]) * rr[kk] * gn + bn;
        g_xln[((size_t)b * K_ + k0 + kk) * N_ + n2] = v;
    }
}

// ---------------- K5: mixed = LN( x + 0.5*rule + 0.5*kron , n1) ----------------
__global__ void k_mixed(const float* __restrict__ x,
                        const float* __restrict__ n1g, const float* __restrict__ n1b) {
    int row = blockIdx.x;
    int b = row >> 5, l = row & 31;
    int t = threadIdx.x;
    float v[4];
    float s1 = 0.f, s2 = 0.f;
    #pragma unroll
    for (int e = 0; e < 4; e++) {
        int d = t * 4 + e;
        float rule = x[((size_t)b * L_ + (d >> 5)) * D_ + l * 32 + (d & 31)];
        float kron = g_xglob[(size_t)row * D_ + d];
        float xv   = x[(size_t)row * D_ + d];
        float val = xv + 0.5f * rule + 0.5f * kron;
        v[e] = val; s1 += val; s2 += val * val;
    }
    blockReduce2_256(s1, s2);
    float m = s1 * (1.f / D_);
    float var = s2 * (1.f / D_) - m * m;
    float rs = rsqrtf(var + 1e-5f);
    #pragma unroll
    for (int e = 0; e < 4; e++) {
        int d = t * 4 + e;
        g_mixed[(size_t)row * D_ + d] = (v[e] - m) * rs * n1g[d] + n1b[d];
    }
}

// ---------------- generic cp.async pipelined fp16 tensor-core GEMM (fp32 A) ------
// mode 2: xglob A=g_xln rows [64x256] @ g_A [256x128tile] -> g_xglob
// mode 3: xloc  A=g_xr(:,n,:) [64x128] @ g_W(n)[128x128], winv computed in-kernel
#define STAGES   4
#define STG_AW   40
#define STG_BW   132
#define STG_AB   10240
#define STG_BYTES 27136
#define GEMM_SMEM (STAGES * STG_BYTES)

__global__ __launch_bounds__(256, 2) void k_gemm(int mode) {
    extern __shared__ float sm[];
    __shared__ float winv_s[128];
    unsigned smem_u32 = (unsigned)__cvta_generic_to_shared(sm);

    int bx  = blockIdx.x;
    int nt0 = blockIdx.y * 128;
    int t   = threadIdx.x;

    const float* Ap; long lda, ostride; int Kdim, width;
    const float* Bp; float* Op; bool use_sc = false;
    if (mode == 2) {
        Ap = g_xln + (size_t)bx * 64 * N_; lda = N_; Kdim = N_; width = N_;
        Bp = g_A + nt0;
        Op = g_xglob + (size_t)bx * 64 * N_ + nt0;
        ostride = N_;
    } else {
        Ap = g_xr + (size_t)bx * K_; lda = (long)N_ * K_; Kdim = K_; width = K_;
        Bp = g_W + (size_t)bx * K_ * K_;
        Op = g_xloc + (size_t)bx * K_;
        ostride = (long)N_ * K_;
        use_sc = true;
        // compute this n's 128 inverse column norms from partial sums
        if (t < 128) {
            float ss = 0.f;
            #pragma unroll
            for (int s = 0; s < 8; s++) ss += g_wpart[s][bx * K_ + t];
            winv_s[t] = 1.f / fmaxf(sqrtf(ss), 1e-12f);
        }
    }
    int nit = Kdim / 32;

    int lane = t & 31, wid = t >> 5;
    int g = lane >> 2, tg = lane & 3;
    int wm = (wid & 1) * 32;
    int wn = (wid >> 1) * 32;

    float acc[2][4][4];
    #pragma unroll
    for (int mt = 0; mt < 2; mt++)
        #pragma unroll
        for (int nt = 0; nt < 4; nt++)
            #pragma unroll
            for (int e = 0; e < 4; e++) acc[mt][nt][e] = 0.f;

    auto issue = [&](int s) {
        if (s < nit) {
            int k0 = s * 32;
            unsigned base = smem_u32 + (s % STAGES) * STG_BYTES;
            #pragma unroll
            for (int i = 0; i < 2; i++) {
                int q = t + i * 256;
                int m = q >> 3, f4 = q & 7;
                unsigned dst = base + (unsigned)(m * STG_AW + f4 * 4) * 4u;
                const float* src = Ap + (size_t)m * lda + k0 + f4 * 4;
                asm volatile("cp.async.cg.shared.global [%0], [%1], 16;" :: "r"(dst), "l"(src));
            }
            #pragma unroll
            for (int i = 0; i < 4; i++) {
                int q = t + i * 256;
                int k = q >> 5, n4 = (q & 31) * 4;
                unsigned dst = base + STG_AB + (unsigned)(k * STG_BW + n4) * 4u;
                const float* src = Bp + (size_t)(k0 + k) * width + n4;
                asm volatile("cp.async.cg.shared.global [%0], [%1], 16;" :: "r"(dst), "l"(src));
            }
        }
        asm volatile("cp.async.commit_group;");
    };

    issue(0); issue(1); issue(2);

    for (int it = 0; it < nit; it++) {
        asm volatile("cp.async.wait_group 2;");
        __syncthreads();
        issue(it + 3);

        const float* Af = sm + (size_t)(it % STAGES) * (STG_BYTES / 4);
        const float* Bf = Af + STG_AB / 4;

        #pragma unroll
        for (int s = 0; s < 2; s++) {
            int kp0 = s * 8 + tg, kp1 = kp0 + 4;
            unsigned af[2][4];
            #pragma unroll
            for (int mt = 0; mt < 2; mt++) {
                int r0 = wm + mt * 16 + g, r1 = r0 + 8;
                float2 a00 = *(const float2*)&Af[r0 * STG_AW + 2 * kp0];
                float2 a10 = *(const float2*)&Af[r1 * STG_AW + 2 * kp0];
                float2 a01 = *(const float2*)&Af[r0 * STG_AW + 2 * kp1];
                float2 a11 = *(const float2*)&Af[r1 * STG_AW + 2 * kp1];
                af[mt][0] = pack16(a00.x, a00.y);
                af[mt][1] = pack16(a10.x, a10.y);
                af[mt][2] = pack16(a01.x, a01.y);
                af[mt][3] = pack16(a11.x, a11.y);
            }
            #pragma unroll
            for (int nt = 0; nt < 4; nt++) {
                int cn = wn + nt * 8 + g;
                unsigned b0 = pack16(Bf[(2 * kp0) * STG_BW + cn], Bf[(2 * kp0 + 1) * STG_BW + cn]);
                unsigned b1 = pack16(Bf[(2 * kp1) * STG_BW + cn], Bf[(2 * kp1 + 1) * STG_BW + cn]);
                mma16816(acc[0][nt], af[0], b0, b1);
                mma16816(acc[1][nt], af[1], b0, b1);
            }
        }
        __syncthreads();
    }

    #pragma unroll
    for (int mt = 0; mt < 2; mt++) {
        int r0 = wm + mt * 16 + g;
        #pragma unroll
        for (int nt = 0; nt < 4; nt++) {
            int c = wn + nt * 8 + tg * 2;
            float v0 = acc[mt][nt][0], v1 = acc[mt][nt][1];
            float v2 = acc[mt][nt][2], v3 = acc[mt][nt][3];
            if (use_sc) {
                float s0 = winv_s[c], s1v = winv_s[c + 1];
                v0 *= s0; v1 *= s1v; v2 *= s0; v3 *= s1v;
            }
            float* p0 = Op + (size_t)r0 * ostride + c;
            float* p1 = Op + (size_t)(r0 + 8) * ostride + c;
            *(float2*)p0 = make_float2(v0, v1);
            *(float2*)p1 = make_float2(v2, v3);
        }
    }
}

// ---------------- fused gate+up+silu GEMM -> g_H (fp16) ----------------
__global__ __launch_bounds__(256, 2) void k_gu(const float* __restrict__ Wg,
                                               const float* __restrict__ Wu) {
    extern __shared__ float sm[];
    unsigned smem_u32 = (unsigned)__cvta_generic_to_shared(sm);

    int l    = blockIdx.x;
    int ntg0 = blockIdx.y * 64;
    int t    = threadIdx.x;

    const float* Ap  = g_mixed + (size_t)l * D_;
    const long  lda  = (long)L_ * D_;
    const float* Bg  = Wg + (size_t)l * D_ * DFF + ntg0;
    const float* Bu  = Wu + (size_t)l * D_ * DFF + ntg0;
    __half* Op       = g_H + (size_t)l * DFF + ntg0;
    const int nit    = D_ / 32;

    int lane = t & 31, wid = t >> 5;
    int g = lane >> 2, tg = lane & 3;
    int wm = (wid & 1) * 32;
    int wn = (wid >> 1) * 16;

    float ag[2][2][4], au[2][2][4];
    #pragma unroll
    for (int mt = 0; mt < 2; mt++)
        #pragma unroll
        for (int nt = 0; nt < 2; nt++)
            #pragma unroll
            for (int e = 0; e < 4; e++) { ag[mt][nt][e] = 0.f; au[mt][nt][e] = 0.f; }

    auto issue = [&](int s) {
        if (s < nit) {
            int k0 = s * 32;
            unsigned base = smem_u32 + (s % STAGES) * STG_BYTES;
            #pragma unroll
            for (int i = 0; i < 2; i++) {
                int q = t + i * 256;
                int m = q >> 3, f4 = q & 7;
                unsigned dst = base + (unsigned)(m * STG_AW + f4 * 4) * 4u;
                const float* src = Ap + (size_t)m * lda + k0 + f4 * 4;
                asm volatile("cp.async.cg.shared.global [%0], [%1], 16;" :: "r"(dst), "l"(src));
            }
            #pragma unroll
            for (int i = 0; i < 2; i++) {
                int q = t + i * 256;
                int k = q >> 4, n4 = (q & 15) * 4;
                unsigned dstg = base + STG_AB + (unsigned)(k * STG_BW + n4) * 4u;
                unsigned dstu = base + STG_AB + (unsigned)(k * STG_BW + 64 + n4) * 4u;
                const float* sg = Bg + (size_t)(k0 + k) * DFF + n4;
                const float* su = Bu + (size_t)(k0 + k) * DFF + n4;
                asm volatile("cp.async.cg.shared.global [%0], [%1], 16;" :: "r"(dstg), "l"(sg));
                asm volatile("cp.async.cg.shared.global [%0], [%1], 16;" :: "r"(dstu), "l"(su));
            }
        }
        asm volatile("cp.async.commit_group;");
    };

    issue(0); issue(1); issue(2);

    for (int it = 0; it < nit; it++) {
        asm volatile("cp.async.wait_group 2;");
        __syncthreads();
        issue(it + 3);

        const float* Af = sm + (size_t)(it % STAGES) * (STG_BYTES / 4);
        const float* Bf = Af + STG_AB / 4;

        #pragma unroll
        for (int s = 0; s < 2; s++) {
            int kp0 = s * 8 + tg, kp1 = kp0 + 4;
            unsigned af[2][4];
            #pragma unroll
            for (int mt = 0; mt < 2; mt++) {
                int r0 = wm + mt * 16 + g, r1 = r0 + 8;
                float2 a00 = *(const float2*)&Af[r0 * STG_AW + 2 * kp0];
                float2 a10 = *(const float2*)&Af[r1 * STG_AW + 2 * kp0];
                float2 a01 = *(const float2*)&Af[r0 * STG_AW + 2 * kp1];
                float2 a11 = *(const float2*)&Af[r1 * STG_AW + 2 * kp1];
                af[mt][0] = pack16(a00.x, a00.y);
                af[mt][1] = pack16(a10.x, a10.y);
                af[mt][2] = pack16(a01.x, a01.y);
                af[mt][3] = pack16(a11.x, a11.y);
            }
            #pragma unroll
            for (int nt = 0; nt < 2; nt++) {
                int cn = wn + nt * 8 + g;
                unsigned bg0 = pack16(Bf[(2 * kp0) * STG_BW + cn], Bf[(2 * kp0 + 1) * STG_BW + cn]);
                unsigned bg1 = pack16(Bf[(2 * kp1) * STG_BW + cn], Bf[(2 * kp1 + 1) * STG_BW + cn]);
                unsigned bu0 = pack16(Bf[(2 * kp0) * STG_BW + 64 + cn], Bf[(2 * kp0 + 1) * STG_BW + 64 + cn]);
                unsigned bu1 = pack16(Bf[(2 * kp1) * STG_BW + 64 + cn], Bf[(2 * kp1 + 1) * STG_BW + 64 + cn]);
                mma16816(ag[0][nt], af[0], bg0, bg1);
                mma16816(ag[1][nt], af[1], bg0, bg1);
                mma16816(au[0][nt], af[0], bu0, bu1);
                mma16816(au[1][nt], af[1], bu0, bu1);
            }
        }
        __syncthreads();
    }

    const long ostride = (long)L_ * DFF;
    #pragma unroll
    for (int mt = 0; mt < 2; mt++) {
        int r0 = wm + mt * 16 + g;
        #pragma unroll
        for (int nt = 0; nt < 2; nt++) {
            int c = wn + nt * 8 + tg * 2;
            float h0 = ag[mt][nt][0] / (1.f + __expf(-ag[mt][nt][0])) * au[mt][nt][0];
            float h1 = ag[mt][nt][1] / (1.f + __expf(-ag[mt][nt][1])) * au[mt][nt][1];
            float h2 = ag[mt][nt][2] / (1.f + __expf(-ag[mt][nt][2])) * au[mt][nt][2];
            float h3 = ag[mt][nt][3] / (1.f + __expf(-ag[mt][nt][3])) * au[mt][nt][3];
            *(__half2*)(Op + (size_t)r0 * ostride + c)       = __floats2half2_rn(h0, h1);
            *(__half2*)(Op + (size_t)(r0 + 8) * ostride + c) = __floats2half2_rn(h2, h3);
        }
    }
}

// ---------------- down GEMM: A = g_H fp16 [64x2048] @ W_down fp32 -> g_ffn ------
#define DN_AW   20
#define DN_AB   5120
#define DN_STG  (DN_AB + 16896)     // 22016
#define DN_SMEM (STAGES * DN_STG)   // 88064

__global__ __launch_bounds__(256, 2) void k_dn(const float* __restrict__ Wd) {
    extern __shared__ float sm[];
    unsigned smem_u32 = (unsigned)__cvta_generic_to_shared(sm);

    int l   = blockIdx.x;
    int nt0 = blockIdx.y * 128;
    int t   = threadIdx.x;

    const __half* Ap = g_H + (size_t)l * DFF;
    const long  lda  = (long)L_ * DFF;
    const float* Bp  = Wd + (size_t)l * DFF * D_ + nt0;
    float* Op        = g_ffn + (size_t)l * D_ + nt0;
    const int nit    = DFF / 32;

    int lane = t & 31, wid = t >> 5;
    int g = lane >> 2, tg = lane & 3;
    int wm = (wid & 1) * 32;
    int wn = (wid >> 1) * 32;

    float acc[2][4][4];
    #pragma unroll
    for (int mt = 0; mt < 2; mt++)
        #pragma unroll
        for (int nt = 0; nt < 4; nt++)
            #pragma unroll
            for (int e = 0; e < 4; e++) acc[mt][nt][e] = 0.f;

    auto issue = [&](int s) {
        if (s < nit) {
            int k0 = s * 32;
            unsigned base = smem_u32 + (s % STAGES) * DN_STG;
            {
                int m = t >> 2, seg = t & 3;
                unsigned dst = base + (unsigned)(m * DN_AW * 4 + seg * 16);
                const __half* src = Ap + (size_t)m * lda + k0 + seg * 8;
                asm volatile("cp.async.cg.shared.global [%0], [%1], 16;" :: "r"(dst), "l"(src));
            }
            #pragma unroll
            for (int i = 0; i < 4; i++) {
                int q = t + i * 256;
                int k = q >> 5, n4 = (q & 31) * 4;
                unsigned dst = base + DN_AB + (unsigned)(k * STG_BW + n4) * 4u;
                const float* src = Bp + (size_t)(k0 + k) * D_ + n4;
                asm volatile("cp.async.cg.shared.global [%0], [%1], 16;" :: "r"(dst), "l"(src));
            }
        }
        asm volatile("cp.async.commit_group;");
    };

    issue(0); issue(1); issue(2);

    for (int it = 0; it < nit; it++) {
        asm volatile("cp.async.wait_group 2;");
        __syncthreads();
        issue(it + 3);

        const unsigned* Au = (const unsigned*)(sm + (size_t)(it % STAGES) * (DN_STG / 4));
        const float* Bf = sm + (size_t)(it % STAGES) * (DN_STG / 4) + DN_AB / 4;

        #pragma unroll
        for (int s = 0; s < 2; s++) {
            int kp0 = s * 8 + tg, kp1 = kp0 + 4;
            unsigned af[2][4];
            #pragma unroll
            for (int mt = 0; mt < 2; mt++) {
                int r0 = wm + mt * 16 + g, r1 = r0 + 8;
                af[mt][0] = Au[r0 * DN_AW + kp0];
                af[mt][1] = Au[r1 * DN_AW + kp0];
                af[mt][2] = Au[r0 * DN_AW + kp1];
                af[mt][3] = Au[r1 * DN_AW + kp1];
            }
            #pragma unroll
            for (int nt = 0; nt < 4; nt++) {
                int cn = wn + nt * 8 + g;
                unsigned b0 = pack16(Bf[(2 * kp0) * STG_BW + cn], Bf[(2 * kp0 + 1) * STG_BW + cn]);
                unsigned b1 = pack16(Bf[(2 * kp1) * STG_BW + cn], Bf[(2 * kp1 + 1) * STG_BW + cn]);
                mma16816(acc[0][nt], af[0], b0, b1);
                mma16816(acc[1][nt], af[1], b0, b1);
            }
        }
        __syncthreads();
    }

    const long ostride = (long)L_ * D_;
    #pragma unroll
    for (int mt = 0; mt < 2; mt++) {
        int r0 = wm + mt * 16 + g;
        #pragma unroll
        for (int nt = 0; nt < 4; nt++) {
            int c = wn + nt * 8 + tg * 2;
            float* p0 = Op + (size_t)r0 * ostride + c;
            float* p1 = Op + (size_t)(r0 + 8) * ostride + c;
            *(float2*)p0 = make_float2(acc[mt][nt][0], acc[mt][nt][1]);
            *(float2*)p1 = make_float2(acc[mt][nt][2], acc[mt][nt][3]);
        }
    }
}

// ---------------- K8: out = LN(mixed+ffn, n2); y_out = y + ffn ----------------
__global__ void k_final(const float* __restrict__ y,
                        const float* __restrict__ n2g, const float* __restrict__ n2b,
                        float* __restrict__ out) {
    int row = blockIdx.x;
    int t = threadIdx.x;
    size_t base = (size_t)row * D_ + t * 4;
    float4 f4 = *(const float4*)(g_ffn + base);
    float4 m4 = *(const float4*)(g_mixed + base);
    float4 y4 = *(const float4*)(y + base);
    float v[4] = {m4.x + f4.x, m4.y + f4.y, m4.z + f4.z, m4.w + f4.w};
    float fv[4] = {f4.x, f4.y, f4.z, f4.w};
    float yv[4] = {y4.x, y4.y, y4.z, y4.w};
    float s1 = 0.f, s2 = 0.f;
    #pragma unroll
    for (int e = 0; e < 4; e++) { s1 += v[e]; s2 += v[e] * v[e]; }
    blockReduce2_256(s1, s2);
    float m = s1 * (1.f / D_);
    float var = s2 * (1.f / D_) - m * m;
    float rs = rsqrtf(var + 1e-5f);
    #pragma unroll
    for (int e = 0; e < 4; e++) {
        int d = t * 4 + e;
        out[base + e] = (v[e] - m) * rs * n2g[d] + n2b[d];
        out[(size_t)B_ * L_ * D_ + base + e] = yv[e] + fv[e];
    }
}

// ---------------- launch ----------------
extern "C" void kernel_launch(void* const* d_in, const int* in_sizes, int n_in,
                              void* d_out, int out_size) {
    const float* x       = (const float*)d_in[0];
    const float* y       = (const float*)d_in[1];
    const float* A_log   = (const float*)d_in[2];
    const float* W_1     = (const float*)d_in[3];
    const float* W_V     = (const float*)d_in[4];
    const float* kn1_g   = (const float*)d_in[5];
    const float* kn1_b   = (const float*)d_in[6];
    const float* kn2_g   = (const float*)d_in[7];
    const float* kn2_b   = (const float*)d_in[8];
    const float* W_gate  = (const float*)d_in[9];
    const float* W_up    = (const float*)d_in[10];
    const float* W_down  = (const float*)d_in[11];
    const float* ny_g    = (const float*)d_in[12];
    const float* ny_b    = (const float*)d_in[13];
    const float* n1_g    = (const float*)d_in[14];
    const float* n1_b    = (const float*)d_in[15];
    const float* n2_g    = (const float*)d_in[16];
    const float* n2_b    = (const float*)d_in[17];
    float* out = (float*)d_out;

    static int smem_set = 0;
    if (!smem_set) {
        cudaFuncSetAttribute(k_gemm, cudaFuncAttributeMaxDynamicSharedMemorySize, GEMM_SMEM);
        cudaFuncSetAttribute(k_gu,   cudaFuncAttributeMaxDynamicSharedMemorySize, GEMM_SMEM);
        cudaFuncSetAttribute(k_dn,   cudaFuncAttributeMaxDynamicSharedMemorySize, DN_SMEM);
        smem_set = 1;
    }

    k_pre<<<2048 + 256 + 128, 256>>>(x, y, ny_g, ny_b, kn1_g, kn1_b, A_log, W_1, W_V);
    k_gemm<<<dim3(N_, 1), 256, GEMM_SMEM>>>(3);                    // x_local (+winv)
    k_trln<<<dim3(4, B_), 256>>>(kn2_g, kn2_b);
    k_gemm<<<dim3(128, 2), 256, GEMM_SMEM>>>(2);                   // x_global
    k_mixed<<<B_ * L_, 256>>>(x, n1_g, n1_b);
    k_gu<<<dim3(L_, DFF / 64), 256, GEMM_SMEM>>>(W_gate, W_up);    // gate+up+silu -> fp16 H
    k_dn<<<dim3(L_, D_ / 128), 256, DN_SMEM>>>(W_down);            // down
    k_final<<<B_ * L_, 256>>>(y, n2_g, n2_b, out);
}

// round 14
// speedup vs baseline: 1.1089x; 1.0422x over previous
#include <cuda_runtime.h>
#include <cuda_fp16.h>
#include <math.h>

#define B_   64
#define L_   32
#define D_   1024
#define DFF  2048
#define K_   128
#define N_   256

// ---------------- scratch (no allocations allowed) ----------------
__device__ float  g_A[N_ * N_];
__device__ float  g_W[N_ * K_ * K_];      // UNNORMALIZED Wl (fp32)
__device__ float  g_wpart[8][N_ * K_];
__device__ __half g_xr[B_ * N_ * K_];     // fp16 kronecker input
__device__ float  g_xloc[B_ * N_ * K_];
__device__ __half g_xln[B_ * K_ * N_];    // fp16 transposed LN
__device__ float  g_xglob[B_ * K_ * N_];
__device__ float  g_mixed[B_ * L_ * D_];  // fp32 (for k_final LN)
__device__ __half g_mixedh[B_ * L_ * D_]; // fp16 copy (for k_gu)
__device__ __half g_H[B_ * L_ * DFF];     // fp16 H = silu(gate)*up
__device__ float  g_ffn[B_ * L_ * D_];

// ---------------- helpers ----------------
__device__ __forceinline__ void blockReduce2_256(float& s1, float& s2) {
    __shared__ float sh1[8], sh2[8];
    int t = threadIdx.x;
    #pragma unroll
    for (int o = 16; o > 0; o >>= 1) {
        s1 += __shfl_xor_sync(0xffffffffu, s1, o);
        s2 += __shfl_xor_sync(0xffffffffu, s2, o);
    }
    if ((t & 31) == 0) { sh1[t >> 5] = s1; sh2[t >> 5] = s2; }
    __syncthreads();
    float a = 0.f, b = 0.f;
    #pragma unroll
    for (int w = 0; w < 8; w++) { a += sh1[w]; b += sh2[w]; }
    s1 = a; s2 = b;
    __syncthreads();
}

__device__ __forceinline__ unsigned pack16(float x0, float x1) {
    unsigned h;
    asm("cvt.rn.f16x2.f32 %0, %1, %2;" : "=r"(h) : "f"(x1), "f"(x0));
    return h;
}

__device__ __forceinline__ void mma16816(float* c, const unsigned* a, unsigned b0, unsigned b1) {
    asm volatile(
        "mma.sync.aligned.m16n8k16.row.col.f32.f16.f16.f32 "
        "{%0,%1,%2,%3}, {%4,%5,%6,%7}, {%8,%9}, {%0,%1,%2,%3};"
        : "+f"(c[0]), "+f"(c[1]), "+f"(c[2]), "+f"(c[3])
        : "r"(a[0]), "r"(a[1]), "r"(a[2]), "r"(a[3]), "r"(b0), "r"(b1));
}

// ---------------- K_pre: fused xr (2048 blocks) + prepA (256) + prepW1 (128) ----
__global__ void k_pre(const float* __restrict__ x, const float* __restrict__ y,
                      const float* __restrict__ nyg, const float* __restrict__ nyb,
                      const float* __restrict__ kn1g, const float* __restrict__ kn1b,
                      const float* __restrict__ Al,
                      const float* __restrict__ W1, const float* __restrict__ WV) {
    int bx = blockIdx.x;
    int t = threadIdx.x;

    if (bx < 2048) {
        int row = bx;
        float4 yv4 = *(const float4*)(y + (size_t)row * D_ + t * 4);
        float4 xv4 = *(const float4*)(x + (size_t)row * D_ + t * 4);
        float yv[4] = {yv4.x, yv4.y, yv4.z, yv4.w};
        float xv[4] = {xv4.x, xv4.y, xv4.z, xv4.w};
        float s1 = 0.f, s2 = 0.f;
        #pragma unroll
        for (int e = 0; e < 4; e++) { s1 += yv[e]; s2 += yv[e] * yv[e]; }
        blockReduce2_256(s1, s2);
        float m = s1 * (1.f / D_);
        float var = s2 * (1.f / D_) - m * m;
        float rs = rsqrtf(var + 1e-5f);
        float kin[4];
        float ls1 = 0.f, ls2 = 0.f;
        #pragma unroll
        for (int e = 0; e < 4; e++) {
            int d = t * 4 + e;
            float ny = (yv[e] - m) * rs * nyg[d] + nyb[d];
            float kv = xv[e] + ny;
            kin[e] = kv; ls1 += kv; ls2 += kv * kv;
        }
        #pragma unroll
        for (int o = 16; o > 0; o >>= 1) {
            ls1 += __shfl_xor_sync(0xffffffffu, ls1, o);
            ls2 += __shfl_xor_sync(0xffffffffu, ls2, o);
        }
        float lm = ls1 * (1.f / 128.f);
        float lv = ls2 * (1.f / 128.f) - lm * lm;
        float lrs = rsqrtf(lv + 1e-5f);
        float o0, o1, o2, o3;
        {
            int d = t * 4, i = d & 127;
            o0 = (kin[0] - lm) * lrs * kn1g[i] + kn1b[i];
            o1 = (kin[1] - lm) * lrs * kn1g[i + 1] + kn1b[i + 1];
            o2 = (kin[2] - lm) * lrs * kn1g[i + 2] + kn1b[i + 2];
            o3 = (kin[3] - lm) * lrs * kn1g[i + 3] + kn1b[i + 3];
        }
        __half2* p = (__half2*)(g_xr + (size_t)row * D_ + t * 4);
        p[0] = __floats2half2_rn(o0, o1);
        p[1] = __floats2half2_rn(o2, o3);
    } else if (bx < 2048 + 256) {
        int j = bx - 2048;
        float v = Al[t * N_ + j];
        float s1 = v * v, s2 = 0.f;
        blockReduce2_256(s1, s2);
        float inv = 1.f / fmaxf(sqrtf(s1), 1e-12f);
        g_A[t * N_ + j] = v * inv;
    } else {
        int bb = bx - 2048 - 256;
        int tt = bb >> 3, is = bb & 7;
        __shared__ float w1s[16][8];
        if (t < 128) w1s[t >> 3][t & 7] = W1[(tt * 16 + (t >> 3)) * 8 + (t & 7)];
        __syncthreads();
        if (t < 128) {
            int o = t;
            float ss[16];
            #pragma unroll
            for (int tl = 0; tl < 16; tl++) ss[tl] = 0.f;
            for (int ii = 0; ii < 16; ii++) {
                int i = is * 16 + ii;
                float wv[8];
                #pragma unroll
                for (int k = 0; k < 8; k++) wv[k] = WV[((size_t)k * K_ + i) * K_ + o];
                #pragma unroll
                for (int tl = 0; tl < 16; tl++) {
                    float wl = 0.f;
                    #pragma unroll
                    for (int k = 0; k < 8; k++) wl += w1s[tl][k] * wv[k];
                    ss[tl] += wl * wl;
                    g_W[((size_t)(tt * 16 + tl) * K_ + i) * K_ + o] = wl;
                }
            }
            #pragma unroll
            for (int tl = 0; tl < 16; tl++)
                g_wpart[is][(tt * 16 + tl) * K_ + o] = ss[tl];
        }
    }
}

// ---------------- K4a: transpose + LN over N (kn2) -> fp16 ----------------
__global__ void k_trln(const float* __restrict__ kn2g, const float* __restrict__ kn2b) {
    int k0 = blockIdx.x * 32;
    int b  = blockIdx.y;
    int t  = threadIdx.x;
    __shared__ float tr[32][264];
    __shared__ float mm[32], rr[32];
    for (int q = t; q < 2048; q += 256) {
        int n = q >> 3, f = q & 7;
        float4 v = *(const float4*)&g_xloc[((size_t)b * N_ + n) * K_ + k0 + f * 4];
        tr[f * 4 + 0][n] = v.x; tr[f * 4 + 1][n] = v.y;
        tr[f * 4 + 2][n] = v.z; tr[f * 4 + 3][n] = v.w;
    }
    __syncthreads();
    int k = t >> 3, s = t & 7;
    float s1 = 0.f, s2 = 0.f;
    #pragma unroll 8
    for (int j = 0; j < 32; j++) {
        float v = tr[k][s + 8 * j];
        s1 += v; s2 += v * v;
    }
    #pragma unroll
    for (int off = 4; off > 0; off >>= 1) {
        s1 += __shfl_xor_sync(0xffffffffu, s1, off);
        s2 += __shfl_xor_sync(0xffffffffu, s2, off);
    }
    if (s == 0) {
        float m = s1 * (1.f / N_);
        float var = s2 * (1.f / N_) - m * m;
        mm[k] = m; rr[k] = rsqrtf(var + 1e-5f);
    }
    __syncthreads();
    int n2 = t;
    float gn = kn2g[n2], bn = kn2b[n2];
    #pragma unroll 4
    for (int kk = 0; kk < 32; kk++) {
        float v = (tr[kk][n2] - mm[kk]) * rr[kk] * gn + bn;
        g_xln[((size_t)b * K_ + k0 + kk) * N_ + n2] = __float2half(v);
    }
}

// ---------------- K5: mixed = LN(...) -> fp32 + fp16 copy ----------------
__global__ void k_mixed(const float* __restrict__ x,
                        const float* __restrict__ n1g, const float* __restrict__ n1b) {
    int row = blockIdx.x;
    int b = row >> 5, l = row & 31;
    int t = threadIdx.x;
    float v[4];
    float s1 = 0.f, s2 = 0.f;
    #pragma unroll
    for (int e = 0; e < 4; e++) {
        int d = t * 4 + e;
        float rule = x[((size_t)b * L_ + (d >> 5)) * D_ + l * 32 + (d & 31)];
        float kron = g_xglob[(size_t)row * D_ + d];
        float xv   = x[(size_t)row * D_ + d];
        float val = xv + 0.5f * rule + 0.5f * kron;
        v[e] = val; s1 += val; s2 += val * val;
    }
    blockReduce2_256(s1, s2);
    float m = s1 * (1.f / D_);
    float var = s2 * (1.f / D_) - m * m;
    float rs = rsqrtf(var + 1e-5f);
    float o[4];
    #pragma unroll
    for (int e = 0; e < 4; e++) {
        int d = t * 4 + e;
        o[e] = (v[e] - m) * rs * n1g[d] + n1b[d];
        g_mixed[(size_t)row * D_ + d] = o[e];
    }
    __half2* hp = (__half2*)(g_mixedh + (size_t)row * D_ + t * 4);
    hp[0] = __floats2half2_rn(o[0], o[1]);
    hp[1] = __floats2half2_rn(o[2], o[3]);
}

// ---------------- generic fp16-A cp.async pipelined tensor-core GEMM ------------
// A fp16 in smem: 64 rows x 32 halfs, row stride 20 u32. B fp32: 32 x 128 pad 132.
// mode 1: down  A=g_H(l) [64x2048] @ Wd(l)[2048x128tile] -> g_ffn
// mode 2: xglob A=g_xln rows [64x256] @ g_A [256x128tile] -> g_xglob
// mode 3: xloc  A=g_xr(:,n,:) [64x128] @ g_W(n)[128x128], winv in-kernel -> g_xloc
#define STAGES   4
#define STG_BW   132
#define G_AW     20
#define G_AB     5120
#define G_STG    (G_AB + 16896)     // 22016
#define G_SMEM   (STAGES * G_STG)   // 88064

__global__ __launch_bounds__(256, 2) void k_gemm(const float* __restrict__ Wd, int mode) {
    extern __shared__ float sm[];
    __shared__ float winv_s[128];
    unsigned smem_u32 = (unsigned)__cvta_generic_to_shared(sm);

    int bx  = blockIdx.x;
    int nt0 = blockIdx.y * 128;
    int t   = threadIdx.x;

    const __half* Ap; long lda, ostride; int Kdim, width;
    const float* Bp; float* Op; bool use_sc = false;
    if (mode == 1) {
        Ap = g_H + (size_t)bx * DFF; lda = (long)L_ * DFF; Kdim = DFF; width = D_;
        Bp = Wd + (size_t)bx * DFF * D_ + nt0;
        Op = g_ffn + (size_t)bx * D_ + nt0;
        ostride = (long)L_ * D_;
    } else if (mode == 2) {
        Ap = g_xln + (size_t)bx * 64 * N_; lda = N_; Kdim = N_; width = N_;
        Bp = g_A + nt0;
        Op = g_xglob + (size_t)bx * 64 * N_ + nt0;
        ostride = N_;
    } else {
        Ap = g_xr + (size_t)bx * K_; lda = (long)N_ * K_; Kdim = K_; width = K_;
        Bp = g_W + (size_t)bx * K_ * K_;
        Op = g_xloc + (size_t)bx * K_;
        ostride = (long)N_ * K_;
        use_sc = true;
        if (t < 128) {
            float ss = 0.f;
            #pragma unroll
            for (int s = 0; s < 8; s++) ss += g_wpart[s][bx * K_ + t];
            winv_s[t] = 1.f / fmaxf(sqrtf(ss), 1e-12f);
        }
    }
    int nit = Kdim / 32;

    int lane = t & 31, wid = t >> 5;
    int g = lane >> 2, tg = lane & 3;
    int wm = (wid & 1) * 32;
    int wn = (wid >> 1) * 32;

    float acc[2][4][4];
    #pragma unroll
    for (int mt = 0; mt < 2; mt++)
        #pragma unroll
        for (int nt = 0; nt < 4; nt++)
            #pragma unroll
            for (int e = 0; e < 4; e++) acc[mt][nt][e] = 0.f;

    auto issue = [&](int s) {
        if (s < nit) {
            int k0 = s * 32;
            unsigned base = smem_u32 + (s % STAGES) * G_STG;
            {
                int m = t >> 2, seg = t & 3;
                unsigned dst = base + (unsigned)(m * G_AW * 4 + seg * 16);
                const __half* src = Ap + (size_t)m * lda + k0 + seg * 8;
                asm volatile("cp.async.cg.shared.global [%0], [%1], 16;" :: "r"(dst), "l"(src));
            }
            #pragma unroll
            for (int i = 0; i < 4; i++) {
                int q = t + i * 256;
                int k = q >> 5, n4 = (q & 31) * 4;
                unsigned dst = base + G_AB + (unsigned)(k * STG_BW + n4) * 4u;
                const float* src = Bp + (size_t)(k0 + k) * width + n4;
                asm volatile("cp.async.cg.shared.global [%0], [%1], 16;" :: "r"(dst), "l"(src));
            }
        }
        asm volatile("cp.async.commit_group;");
    };

    issue(0); issue(1); issue(2);

    for (int it = 0; it < nit; it++) {
        asm volatile("cp.async.wait_group 2;");
        __syncthreads();
        issue(it + 3);

        const unsigned* Au = (const unsigned*)(sm + (size_t)(it % STAGES) * (G_STG / 4));
        const float* Bf = sm + (size_t)(it % STAGES) * (G_STG / 4) + G_AB / 4;

        #pragma unroll
        for (int s = 0; s < 2; s++) {
            int kp0 = s * 8 + tg, kp1 = kp0 + 4;
            unsigned af[2][4];
            #pragma unroll
            for (int mt = 0; mt < 2; mt++) {
                int r0 = wm + mt * 16 + g, r1 = r0 + 8;
                af[mt][0] = Au[r0 * G_AW + kp0];
                af[mt][1] = Au[r1 * G_AW + kp0];
                af[mt][2] = Au[r0 * G_AW + kp1];
                af[mt][3] = Au[r1 * G_AW + kp1];
            }
            #pragma unroll
            for (int nt = 0; nt < 4; nt++) {
                int cn = wn + nt * 8 + g;
                unsigned b0 = pack16(Bf[(2 * kp0) * STG_BW + cn], Bf[(2 * kp0 + 1) * STG_BW + cn]);
                unsigned b1 = pack16(Bf[(2 * kp1) * STG_BW + cn], Bf[(2 * kp1 + 1) * STG_BW + cn]);
                mma16816(acc[0][nt], af[0], b0, b1);
                mma16816(acc[1][nt], af[1], b0, b1);
            }
        }
        __syncthreads();
    }

    #pragma unroll
    for (int mt = 0; mt < 2; mt++) {
        int r0 = wm + mt * 16 + g;
        #pragma unroll
        for (int nt = 0; nt < 4; nt++) {
            int c = wn + nt * 8 + tg * 2;
            float v0 = acc[mt][nt][0], v1 = acc[mt][nt][1];
            float v2 = acc[mt][nt][2], v3 = acc[mt][nt][3];
            if (use_sc) {
                float s0 = winv_s[c], s1v = winv_s[c + 1];
                v0 *= s0; v1 *= s1v; v2 *= s0; v3 *= s1v;
            }
            float* p0 = Op + (size_t)r0 * ostride + c;
            float* p1 = Op + (size_t)(r0 + 8) * ostride + c;
            *(float2*)p0 = make_float2(v0, v1);
            *(float2*)p1 = make_float2(v2, v3);
        }
    }
}

// ---------------- fused gate+up+silu GEMM (fp16 A) -> g_H fp16 ----------------
__global__ __launch_bounds__(256, 2) void k_gu(const float* __restrict__ Wg,
                                               const float* __restrict__ Wu) {
    extern __shared__ float sm[];
    unsigned smem_u32 = (unsigned)__cvta_generic_to_shared(sm);

    int l    = blockIdx.x;
    int ntg0 = blockIdx.y * 64;
    int t    = threadIdx.x;

    const __half* Ap = g_mixedh + (size_t)l * D_;
    const long  lda  = (long)L_ * D_;
    const float* Bg  = Wg + (size_t)l * D_ * DFF + ntg0;
    const float* Bu  = Wu + (size_t)l * D_ * DFF + ntg0;
    __half* Op       = g_H + (size_t)l * DFF + ntg0;
    const int nit    = D_ / 32;

    int lane = t & 31, wid = t >> 5;
    int g = lane >> 2, tg = lane & 3;
    int wm = (wid & 1) * 32;
    int wn = (wid >> 1) * 16;

    float ag[2][2][4], au[2][2][4];
    #pragma unroll
    for (int mt = 0; mt < 2; mt++)
        #pragma unroll
        for (int nt = 0; nt < 2; nt++)
            #pragma unroll
            for (int e = 0; e < 4; e++) { ag[mt][nt][e] = 0.f; au[mt][nt][e] = 0.f; }

    auto issue = [&](int s) {
        if (s < nit) {
            int k0 = s * 32;
            unsigned base = smem_u32 + (s % STAGES) * G_STG;
            {
                int m = t >> 2, seg = t & 3;
                unsigned dst = base + (unsigned)(m * G_AW * 4 + seg * 16);
                const __half* src = Ap + (size_t)m * lda + k0 + seg * 8;
                asm volatile("cp.async.cg.shared.global [%0], [%1], 16;" :: "r"(dst), "l"(src));
            }
            #pragma unroll
            for (int i = 0; i < 2; i++) {
                int q = t + i * 256;
                int k = q >> 4, n4 = (q & 15) * 4;
                unsigned dstg = base + G_AB + (unsigned)(k * STG_BW + n4) * 4u;
                unsigned dstu = base + G_AB + (unsigned)(k * STG_BW + 64 + n4) * 4u;
                const float* sg = Bg + (size_t)(k0 + k) * DFF + n4;
                const float* su = Bu + (size_t)(k0 + k) * DFF + n4;
                asm volatile("cp.async.cg.shared.global [%0], [%1], 16;" :: "r"(dstg), "l"(sg));
                asm volatile("cp.async.cg.shared.global [%0], [%1], 16;" :: "r"(dstu), "l"(su));
            }
        }
        asm volatile("cp.async.commit_group;");
    };

    issue(0); issue(1); issue(2);

    for (int it = 0; it < nit; it++) {
        asm volatile("cp.async.wait_group 2;");
        __syncthreads();
        issue(it + 3);

        const unsigned* Au2 = (const unsigned*)(sm + (size_t)(it % STAGES) * (G_STG / 4));
        const float* Bf = sm + (size_t)(it % STAGES) * (G_STG / 4) + G_AB / 4;

        #pragma unroll
        for (int s = 0; s < 2; s++) {
            int kp0 = s * 8 + tg, kp1 = kp0 + 4;
            unsigned af[2][4];
            #pragma unroll
            for (int mt = 0; mt < 2; mt++) {
                int r0 = wm + mt * 16 + g, r1 = r0 + 8;
                af[mt][0] = Au2[r0 * G_AW + kp0];
                af[mt][1] = Au2[r1 * G_AW + kp0];
                af[mt][2] = Au2[r0 * G_AW + kp1];
                af[mt][3] = Au2[r1 * G_AW + kp1];
            }
            #pragma unroll
            for (int nt = 0; nt < 2; nt++) {
                int cn = wn + nt * 8 + g;
                unsigned bg0 = pack16(Bf[(2 * kp0) * STG_BW + cn], Bf[(2 * kp0 + 1) * STG_BW + cn]);
                unsigned bg1 = pack16(Bf[(2 * kp1) * STG_BW + cn], Bf[(2 * kp1 + 1) * STG_BW + cn]);
                unsigned bu0 = pack16(Bf[(2 * kp0) * STG_BW + 64 + cn], Bf[(2 * kp0 + 1) * STG_BW + 64 + cn]);
                unsigned bu1 = pack16(Bf[(2 * kp1) * STG_BW + 64 + cn], Bf[(2 * kp1 + 1) * STG_BW + 64 + cn]);
                mma16816(ag[0][nt], af[0], bg0, bg1);
                mma16816(ag[1][nt], af[1], bg0, bg1);
                mma16816(au[0][nt], af[0], bu0, bu1);
                mma16816(au[1][nt], af[1], bu0, bu1);
            }
        }
        __syncthreads();
    }

    const long ostride = (long)L_ * DFF;
    #pragma unroll
    for (int mt = 0; mt < 2; mt++) {
        int r0 = wm + mt * 16 + g;
        #pragma unroll
        for (int nt = 0; nt < 2; nt++) {
            int c = wn + nt * 8 + tg * 2;
            float h0 = ag[mt][nt][0] / (1.f + __expf(-ag[mt][nt][0])) * au[mt][nt][0];
            float h1 = ag[mt][nt][1] / (1.f + __expf(-ag[mt][nt][1])) * au[mt][nt][1];
            float h2 = ag[mt][nt][2] / (1.f + __expf(-ag[mt][nt][2])) * au[mt][nt][2];
            float h3 = ag[mt][nt][3] / (1.f + __expf(-ag[mt][nt][3])) * au[mt][nt][3];
            *(__half2*)(Op + (size_t)r0 * ostride + c)       = __floats2half2_rn(h0, h1);
            *(__half2*)(Op + (size_t)(r0 + 8) * ostride + c) = __floats2half2_rn(h2, h3);
        }
    }
}

// ---------------- K8: out = LN(mixed+ffn, n2); y_out = y + ffn ----------------
__global__ void k_final(const float* __restrict__ y,
                        const float* __restrict__ n2g, const float* __restrict__ n2b,
                        float* __restrict__ out) {
    int row = blockIdx.x;
    int t = threadIdx.x;
    size_t base = (size_t)row * D_ + t * 4;
    float4 f4 = *(const float4*)(g_ffn + base);
    float4 m4 = *(const float4*)(g_mixed + base);
    float4 y4 = *(const float4*)(y + base);
    float v[4] = {m4.x + f4.x, m4.y + f4.y, m4.z + f4.z, m4.w + f4.w};
    float fv[4] = {f4.x, f4.y, f4.z, f4.w};
    float yv[4] = {y4.x, y4.y, y4.z, y4.w};
    float s1 = 0.f, s2 = 0.f;
    #pragma unroll
    for (int e = 0; e < 4; e++) { s1 += v[e]; s2 += v[e] * v[e]; }
    blockReduce2_256(s1, s2);
    float m = s1 * (1.f / D_);
    float var = s2 * (1.f / D_) - m * m;
    float rs = rsqrtf(var + 1e-5f);
    #pragma unroll
    for (int e = 0; e < 4; e++) {
        int d = t * 4 + e;
        out[base + e] = (v[e] - m) * rs * n2g[d] + n2b[d];
        out[(size_t)B_ * L_ * D_ + base + e] = yv[e] + fv[e];
    }
}

// ---------------- launch ----------------
extern "C" void kernel_launch(void* const* d_in, const int* in_sizes, int n_in,
                              void* d_out, int out_size) {
    const float* x       = (const float*)d_in[0];
    const float* y       = (const float*)d_in[1];
    const float* A_log   = (const float*)d_in[2];
    const float* W_1     = (const float*)d_in[3];
    const float* W_V     = (const float*)d_in[4];
    const float* kn1_g   = (const float*)d_in[5];
    const float* kn1_b   = (const float*)d_in[6];
    const float* kn2_g   = (const float*)d_in[7];
    const float* kn2_b   = (const float*)d_in[8];
    const float* W_gate  = (const float*)d_in[9];
    const float* W_up    = (const float*)d_in[10];
    const float* W_down  = (const float*)d_in[11];
    const float* ny_g    = (const float*)d_in[12];
    const float* ny_b    = (const float*)d_in[13];
    const float* n1_g    = (const float*)d_in[14];
    const float* n1_b    = (const float*)d_in[15];
    const float* n2_g    = (const float*)d_in[16];
    const float* n2_b    = (const float*)d_in[17];
    float* out = (float*)d_out;

    static int smem_set = 0;
    if (!smem_set) {
        cudaFuncSetAttribute(k_gemm, cudaFuncAttributeMaxDynamicSharedMemorySize, G_SMEM);
        cudaFuncSetAttribute(k_gu,   cudaFuncAttributeMaxDynamicSharedMemorySize, G_SMEM);
        smem_set = 1;
    }

    k_pre<<<2048 + 256 + 128, 256>>>(x, y, ny_g, ny_b, kn1_g, kn1_b, A_log, W_1, W_V);
    k_gemm<<<dim3(N_, 1), 256, G_SMEM>>>(nullptr, 3);              // x_local (+winv)
    k_trln<<<dim3(4, B_), 256>>>(kn2_g, kn2_b);
    k_gemm<<<dim3(128, 2), 256, G_SMEM>>>(nullptr, 2);             // x_global
    k_mixed<<<B_ * L_, 256>>>(x, n1_g, n1_b);
    k_gu<<<dim3(L_, DFF / 64), 256, G_SMEM>>>(W_gate, W_up);       // gate+up+silu -> fp16 H
    k_gemm<<<dim3(L_, D_ / 128), 256, G_SMEM>>>(W_down, 1);        // down
    k_final<<<B_ * L_, 256>>>(y, n2_g, n2_b, out);
}

// round 15
// speedup vs baseline: 1.1121x; 1.0029x over previous
#include <cuda_runtime.h>
#include <cuda_fp16.h>
#include <math.h>

#define B_   64
#define L_   32
#define D_   1024
#define DFF  2048
#define K_   128
#define N_   256

// ---------------- scratch (no allocations allowed) ----------------
__device__ float  g_A[N_ * N_];
__device__ float  g_W[N_ * K_ * K_];      // UNNORMALIZED Wl (fp32)
__device__ float  g_wpart[8][N_ * K_];
__device__ __half g_xr[B_ * N_ * K_];     // fp16 kronecker input
__device__ __half g_xloc[B_ * N_ * K_];   // fp16 x_local
__device__ __half g_xln[B_ * K_ * N_];    // fp16 transposed LN
__device__ __half g_xglob[B_ * K_ * N_];  // fp16 x_global
__device__ float  g_mixed[B_ * L_ * D_];  // fp32 (for k_final LN)
__device__ __half g_mixedh[B_ * L_ * D_]; // fp16 copy (for k_gu)
__device__ __half g_H[B_ * L_ * DFF];     // fp16 H = silu(gate)*up
__device__ float  g_ffn[B_ * L_ * D_];

// ---------------- helpers ----------------
__device__ __forceinline__ void blockReduce2_256(float& s1, float& s2) {
    __shared__ float sh1[8], sh2[8];
    int t = threadIdx.x;
    #pragma unroll
    for (int o = 16; o > 0; o >>= 1) {
        s1 += __shfl_xor_sync(0xffffffffu, s1, o);
        s2 += __shfl_xor_sync(0xffffffffu, s2, o);
    }
    if ((t & 31) == 0) { sh1[t >> 5] = s1; sh2[t >> 5] = s2; }
    __syncthreads();
    float a = 0.f, b = 0.f;
    #pragma unroll
    for (int w = 0; w < 8; w++) { a += sh1[w]; b += sh2[w]; }
    s1 = a; s2 = b;
    __syncthreads();
}

__device__ __forceinline__ unsigned pack16(float x0, float x1) {
    unsigned h;
    asm("cvt.rn.f16x2.f32 %0, %1, %2;" : "=r"(h) : "f"(x1), "f"(x0));
    return h;
}

__device__ __forceinline__ void mma16816(float* c, const unsigned* a, unsigned b0, unsigned b1) {
    asm volatile(
        "mma.sync.aligned.m16n8k16.row.col.f32.f16.f16.f32 "
        "{%0,%1,%2,%3}, {%4,%5,%6,%7}, {%8,%9}, {%0,%1,%2,%3};"
        : "+f"(c[0]), "+f"(c[1]), "+f"(c[2]), "+f"(c[3])
        : "r"(a[0]), "r"(a[1]), "r"(a[2]), "r"(a[3]), "r"(b0), "r"(b1));
}

// ---------------- K_pre: fused xr (2048 blocks) + prepA (256) + prepW1 (128) ----
__global__ void k_pre(const float* __restrict__ x, const float* __restrict__ y,
                      const float* __restrict__ nyg, const float* __restrict__ nyb,
                      const float* __restrict__ kn1g, const float* __restrict__ kn1b,
                      const float* __restrict__ Al,
                      const float* __restrict__ W1, const float* __restrict__ WV) {
    int bx = blockIdx.x;
    int t = threadIdx.x;

    if (bx < 2048) {
        int row = bx;
        float4 yv4 = *(const float4*)(y + (size_t)row * D_ + t * 4);
        float4 xv4 = *(const float4*)(x + (size_t)row * D_ + t * 4);
        float yv[4] = {yv4.x, yv4.y, yv4.z, yv4.w};
        float xv[4] = {xv4.x, xv4.y, xv4.z, xv4.w};
        float s1 = 0.f, s2 = 0.f;
        #pragma unroll
        for (int e = 0; e < 4; e++) { s1 += yv[e]; s2 += yv[e] * yv[e]; }
        blockReduce2_256(s1, s2);
        float m = s1 * (1.f / D_);
        float var = s2 * (1.f / D_) - m * m;
        float rs = rsqrtf(var + 1e-5f);
        float kin[4];
        float ls1 = 0.f, ls2 = 0.f;
        #pragma unroll
        for (int e = 0; e < 4; e++) {
            int d = t * 4 + e;
            float ny = (yv[e] - m) * rs * nyg[d] + nyb[d];
            float kv = xv[e] + ny;
            kin[e] = kv; ls1 += kv; ls2 += kv * kv;
        }
        #pragma unroll
        for (int o = 16; o > 0; o >>= 1) {
            ls1 += __shfl_xor_sync(0xffffffffu, ls1, o);
            ls2 += __shfl_xor_sync(0xffffffffu, ls2, o);
        }
        float lm = ls1 * (1.f / 128.f);
        float lv = ls2 * (1.f / 128.f) - lm * lm;
        float lrs = rsqrtf(lv + 1e-5f);
        float o0, o1, o2, o3;
        {
            int i = (t * 4) & 127;
            o0 = (kin[0] - lm) * lrs * kn1g[i] + kn1b[i];
            o1 = (kin[1] - lm) * lrs * kn1g[i + 1] + kn1b[i + 1];
            o2 = (kin[2] - lm) * lrs * kn1g[i + 2] + kn1b[i + 2];
            o3 = (kin[3] - lm) * lrs * kn1g[i + 3] + kn1b[i + 3];
        }
        __half2* p = (__half2*)(g_xr + (size_t)row * D_ + t * 4);
        p[0] = __floats2half2_rn(o0, o1);
        p[1] = __floats2half2_rn(o2, o3);
    } else if (bx < 2048 + 256) {
        int j = bx - 2048;
        float v = Al[t * N_ + j];
        float s1 = v * v, s2 = 0.f;
        blockReduce2_256(s1, s2);
        float inv = 1.f / fmaxf(sqrtf(s1), 1e-12f);
        g_A[t * N_ + j] = v * inv;
    } else {
        int bb = bx - 2048 - 256;
        int tt = bb >> 3, is = bb & 7;
        __shared__ float w1s[16][8];
        if (t < 128) w1s[t >> 3][t & 7] = W1[(tt * 16 + (t >> 3)) * 8 + (t & 7)];
        __syncthreads();
        if (t < 128) {
            int o = t;
            float ss[16];
            #pragma unroll
            for (int tl = 0; tl < 16; tl++) ss[tl] = 0.f;
            for (int ii = 0; ii < 16; ii++) {
                int i = is * 16 + ii;
                float wv[8];
                #pragma unroll
                for (int k = 0; k < 8; k++) wv[k] = WV[((size_t)k * K_ + i) * K_ + o];
                #pragma unroll
                for (int tl = 0; tl < 16; tl++) {
                    float wl = 0.f;
                    #pragma unroll
                    for (int k = 0; k < 8; k++) wl += w1s[tl][k] * wv[k];
                    ss[tl] += wl * wl;
                    g_W[((size_t)(tt * 16 + tl) * K_ + i) * K_ + o] = wl;
                }
            }
            #pragma unroll
            for (int tl = 0; tl < 16; tl++)
                g_wpart[is][(tt * 16 + tl) * K_ + o] = ss[tl];
        }
    }
}

// ---------------- K4a: transpose + LN over N (kn2), fp16 in/out ----------------
__global__ void k_trln(const float* __restrict__ kn2g, const float* __restrict__ kn2b) {
    int k0 = blockIdx.x * 32;
    int b  = blockIdx.y;
    int t  = threadIdx.x;
    __shared__ float tr[32][264];
    __shared__ float mm[32], rr[32];
    // each iter: thread t handles row n=t, 8 halfs (16B) at k0 + seg*8
    #pragma unroll
    for (int seg = 0; seg < 4; seg++) {
        const uint4 raw = *(const uint4*)&g_xloc[((size_t)b * N_ + t) * K_ + k0 + seg * 8];
        const __half2* h = (const __half2*)&raw;
        #pragma unroll
        for (int j = 0; j < 4; j++) {
            float2 f = __half22float2(h[j]);
            tr[seg * 8 + j * 2][t]     = f.x;
            tr[seg * 8 + j * 2 + 1][t] = f.y;
        }
    }
    __syncthreads();
    int k = t >> 3, s = t & 7;
    float s1 = 0.f, s2 = 0.f;
    #pragma unroll 8
    for (int j = 0; j < 32; j++) {
        float v = tr[k][s + 8 * j];
        s1 += v; s2 += v * v;
    }
    #pragma unroll
    for (int off = 4; off > 0; off >>= 1) {
        s1 += __shfl_xor_sync(0xffffffffu, s1, off);
        s2 += __shfl_xor_sync(0xffffffffu, s2, off);
    }
    if (s == 0) {
        float m = s1 * (1.f / N_);
        float var = s2 * (1.f / N_) - m * m;
        mm[k] = m; rr[k] = rsqrtf(var + 1e-5f);
    }
    __syncthreads();
    int n2 = t;
    float gn = kn2g[n2], bn = kn2b[n2];
    #pragma unroll 4
    for (int kk = 0; kk < 32; kk++) {
        float v = (tr[kk][n2] - mm[kk]) * rr[kk] * gn + bn;
        g_xln[((size_t)b * K_ + k0 + kk) * N_ + n2] = __float2half(v);
    }
}

// ---------------- K5: mixed = LN(...) -> fp32 + fp16 copy ----------------
__global__ void k_mixed(const float* __restrict__ x,
                        const float* __restrict__ n1g, const float* __restrict__ n1b) {
    int row = blockIdx.x;
    int b = row >> 5, l = row & 31;
    int t = threadIdx.x;
    const __half2* kp = (const __half2*)(g_xglob + (size_t)row * D_ + t * 4);
    float2 k0 = __half22float2(kp[0]);
    float2 k1 = __half22float2(kp[1]);
    float kron[4] = {k0.x, k0.y, k1.x, k1.y};
    float v[4];
    float s1 = 0.f, s2 = 0.f;
    #pragma unroll
    for (int e = 0; e < 4; e++) {
        int d = t * 4 + e;
        float rule = x[((size_t)b * L_ + (d >> 5)) * D_ + l * 32 + (d & 31)];
        float xv   = x[(size_t)row * D_ + d];
        float val = xv + 0.5f * rule + 0.5f * kron[e];
        v[e] = val; s1 += val; s2 += val * val;
    }
    blockReduce2_256(s1, s2);
    float m = s1 * (1.f / D_);
    float var = s2 * (1.f / D_) - m * m;
    float rs = rsqrtf(var + 1e-5f);
    float o[4];
    #pragma unroll
    for (int e = 0; e < 4; e++) {
        int d = t * 4 + e;
        o[e] = (v[e] - m) * rs * n1g[d] + n1b[d];
        g_mixed[(size_t)row * D_ + d] = o[e];
    }
    __half2* hp = (__half2*)(g_mixedh + (size_t)row * D_ + t * 4);
    hp[0] = __floats2half2_rn(o[0], o[1]);
    hp[1] = __floats2half2_rn(o[2], o[3]);
}

// ---------------- generic fp16-A cp.async pipelined tensor-core GEMM ------------
// mode 1: down  A=g_H(l) [64x2048] @ Wd(l)[2048x128tile] -> g_ffn (fp32)
// mode 2: xglob A=g_xln rows [64x256] @ g_A [256x128tile] -> g_xglob (fp16)
// mode 3: xloc  A=g_xr(:,n,:) [64x128] @ g_W(n)[128x128], winv -> g_xloc (fp16)
#define STAGES   4
#define STG_BW   132
#define G_AW     20
#define G_AB     5120
#define G_STG    (G_AB + 16896)     // 22016
#define G_SMEM   (STAGES * G_STG)   // 88064

__global__ __launch_bounds__(256, 2) void k_gemm(const float* __restrict__ Wd, int mode) {
    extern __shared__ float sm[];
    __shared__ float winv_s[128];
    unsigned smem_u32 = (unsigned)__cvta_generic_to_shared(sm);

    int bx  = blockIdx.x;
    int nt0 = blockIdx.y * 128;
    int t   = threadIdx.x;

    const __half* Ap; long lda, ostride; int Kdim, width;
    const float* Bp; float* Op = 0; __half* Oph = 0; bool use_sc = false;
    if (mode == 1) {
        Ap = g_H + (size_t)bx * DFF; lda = (long)L_ * DFF; Kdim = DFF; width = D_;
        Bp = Wd + (size_t)bx * DFF * D_ + nt0;
        Op = g_ffn + (size_t)bx * D_ + nt0;
        ostride = (long)L_ * D_;
    } else if (mode == 2) {
        Ap = g_xln + (size_t)bx * 64 * N_; lda = N_; Kdim = N_; width = N_;
        Bp = g_A + nt0;
        Oph = g_xglob + (size_t)bx * 64 * N_ + nt0;
        ostride = N_;
    } else {
        Ap = g_xr + (size_t)bx * K_; lda = (long)N_ * K_; Kdim = K_; width = K_;
        Bp = g_W + (size_t)bx * K_ * K_;
        Oph = g_xloc + (size_t)bx * K_;
        ostride = (long)N_ * K_;
        use_sc = true;
        if (t < 128) {
            float ss = 0.f;
            #pragma unroll
            for (int s = 0; s < 8; s++) ss += g_wpart[s][bx * K_ + t];
            winv_s[t] = 1.f / fmaxf(sqrtf(ss), 1e-12f);
        }
    }
    int nit = Kdim / 32;

    int lane = t & 31, wid = t >> 5;
    int g = lane >> 2, tg = lane & 3;
    int wm = (wid & 1) * 32;
    int wn = (wid >> 1) * 32;

    float acc[2][4][4];
    #pragma unroll
    for (int mt = 0; mt < 2; mt++)
        #pragma unroll
        for (int nt = 0; nt < 4; nt++)
            #pragma unroll
            for (int e = 0; e < 4; e++) acc[mt][nt][e] = 0.f;

    auto issue = [&](int s) {
        if (s < nit) {
            int k0 = s * 32;
            unsigned base = smem_u32 + (s % STAGES) * G_STG;
            {
                int m = t >> 2, seg = t & 3;
                unsigned dst = base + (unsigned)(m * G_AW * 4 + seg * 16);
                const __half* src = Ap + (size_t)m * lda + k0 + seg * 8;
                asm volatile("cp.async.cg.shared.global [%0], [%1], 16;" :: "r"(dst), "l"(src));
            }
            #pragma unroll
            for (int i = 0; i < 4; i++) {
                int q = t + i * 256;
                int k = q >> 5, n4 = (q & 31) * 4;
                unsigned dst = base + G_AB + (unsigned)(k * STG_BW + n4) * 4u;
                const float* src = Bp + (size_t)(k0 + k) * width + n4;
                asm volatile("cp.async.cg.shared.global [%0], [%1], 16;" :: "r"(dst), "l"(src));
            }
        }
        asm volatile("cp.async.commit_group;");
    };

    issue(0); issue(1); issue(2);

    for (int it = 0; it < nit; it++) {
        asm volatile("cp.async.wait_group 2;");
        __syncthreads();
        issue(it + 3);

        const unsigned* Au = (const unsigned*)(sm + (size_t)(it % STAGES) * (G_STG / 4));
        const float* Bf = sm + (size_t)(it % STAGES) * (G_STG / 4) + G_AB / 4;

        #pragma unroll
        for (int s = 0; s < 2; s++) {
            int kp0 = s * 8 + tg, kp1 = kp0 + 4;
            unsigned af[2][4];
            #pragma unroll
            for (int mt = 0; mt < 2; mt++) {
                int r0 = wm + mt * 16 + g, r1 = r0 + 8;
                af[mt][0] = Au[r0 * G_AW + kp0];
                af[mt][1] = Au[r1 * G_AW + kp0];
                af[mt][2] = Au[r0 * G_AW + kp1];
                af[mt][3] = Au[r1 * G_AW + kp1];
            }
            #pragma unroll
            for (int nt = 0; nt < 4; nt++) {
                int cn = wn + nt * 8 + g;
                unsigned b0 = pack16(Bf[(2 * kp0) * STG_BW + cn], Bf[(2 * kp0 + 1) * STG_BW + cn]);
                unsigned b1 = pack16(Bf[(2 * kp1) * STG_BW + cn], Bf[(2 * kp1 + 1) * STG_BW + cn]);
                mma16816(acc[0][nt], af[0], b0, b1);
                mma16816(acc[1][nt], af[1], b0, b1);
            }
        }
        __syncthreads();
    }

    #pragma unroll
    for (int mt = 0; mt < 2; mt++) {
        int r0 = wm + mt * 16 + g;
        #pragma unroll
        for (int nt = 0; nt < 4; nt++) {
            int c = wn + nt * 8 + tg * 2;
            float v0 = acc[mt][nt][0], v1 = acc[mt][nt][1];
            float v2 = acc[mt][nt][2], v3 = acc[mt][nt][3];
            if (use_sc) {
                float s0 = winv_s[c], s1v = winv_s[c + 1];
                v0 *= s0; v1 *= s1v; v2 *= s0; v3 *= s1v;
            }
            if (mode == 1) {
                float* p0 = Op + (size_t)r0 * ostride + c;
                float* p1 = Op + (size_t)(r0 + 8) * ostride + c;
                *(float2*)p0 = make_float2(v0, v1);
                *(float2*)p1 = make_float2(v2, v3);
            } else {
                *(__half2*)(Oph + (size_t)r0 * ostride + c)       = __floats2half2_rn(v0, v1);
                *(__half2*)(Oph + (size_t)(r0 + 8) * ostride + c) = __floats2half2_rn(v2, v3);
            }
        }
    }
}

// ---------------- fused gate+up+silu GEMM (fp16 A) -> g_H fp16 ----------------
__global__ __launch_bounds__(256, 2) void k_gu(const float* __restrict__ Wg,
                                               const float* __restrict__ Wu) {
    extern __shared__ float sm[];
    unsigned smem_u32 = (unsigned)__cvta_generic_to_shared(sm);

    int l    = blockIdx.x;
    int ntg0 = blockIdx.y * 64;
    int t    = threadIdx.x;

    const __half* Ap = g_mixedh + (size_t)l * D_;
    const long  lda  = (long)L_ * D_;
    const float* Bg  = Wg + (size_t)l * D_ * DFF + ntg0;
    const float* Bu  = Wu + (size_t)l * D_ * DFF + ntg0;
    __half* Op       = g_H + (size_t)l * DFF + ntg0;
    const int nit    = D_ / 32;

    int lane = t & 31, wid = t >> 5;
    int g = lane >> 2, tg = lane & 3;
    int wm = (wid & 1) * 32;
    int wn = (wid >> 1) * 16;

    float ag[2][2][4], au[2][2][4];
    #pragma unroll
    for (int mt = 0; mt < 2; mt++)
        #pragma unroll
        for (int nt = 0; nt < 2; nt++)
            #pragma unroll
            for (int e = 0; e < 4; e++) { ag[mt][nt][e] = 0.f; au[mt][nt][e] = 0.f; }

    auto issue = [&](int s) {
        if (s < nit) {
            int k0 = s * 32;
            unsigned base = smem_u32 + (s % STAGES) * G_STG;
            {
                int m = t >> 2, seg = t & 3;
                unsigned dst = base + (unsigned)(m * G_AW * 4 + seg * 16);
                const __half* src = Ap + (size_t)m * lda + k0 + seg * 8;
                asm volatile("cp.async.cg.shared.global [%0], [%1], 16;" :: "r"(dst), "l"(src));
            }
            #pragma unroll
            for (int i = 0; i < 2; i++) {
                int q = t + i * 256;
                int k = q >> 4, n4 = (q & 15) * 4;
                unsigned dstg = base + G_AB + (unsigned)(k * STG_BW + n4) * 4u;
                unsigned dstu = base + G_AB + (unsigned)(k * STG_BW + 64 + n4) * 4u;
                const float* sg = Bg + (size_t)(k0 + k) * DFF + n4;
                const float* su = Bu + (size_t)(k0 + k) * DFF + n4;
                asm volatile("cp.async.cg.shared.global [%0], [%1], 16;" :: "r"(dstg), "l"(sg));
                asm volatile("cp.async.cg.shared.global [%0], [%1], 16;" :: "r"(dstu), "l"(su));
            }
        }
        asm volatile("cp.async.commit_group;");
    };

    issue(0); issue(1); issue(2);

    for (int it = 0; it < nit; it++) {
        asm volatile("cp.async.wait_group 2;");
        __syncthreads();
        issue(it + 3);

        const unsigned* Au2 = (const unsigned*)(sm + (size_t)(it % STAGES) * (G_STG / 4));
        const float* Bf = sm + (size_t)(it % STAGES) * (G_STG / 4) + G_AB / 4;

        #pragma unroll
        for (int s = 0; s < 2; s++) {
            int kp0 = s * 8 + tg, kp1 = kp0 + 4;
            unsigned af[2][4];
            #pragma unroll
            for (int mt = 0; mt < 2; mt++) {
                int r0 = wm + mt * 16 + g, r1 = r0 + 8;
                af[mt][0] = Au2[r0 * G_AW + kp0];
                af[mt][1] = Au2[r1 * G_AW + kp0];
                af[mt][2] = Au2[r0 * G_AW + kp1];
                af[mt][3] = Au2[r1 * G_AW + kp1];
            }
            #pragma unroll
            for (int nt = 0; nt < 2; nt++) {
                int cn = wn + nt * 8 + g;
                unsigned bg0 = pack16(Bf[(2 * kp0) * STG_BW + cn], Bf[(2 * kp0 + 1) * STG_BW + cn]);
                unsigned bg1 = pack16(Bf[(2 * kp1) * STG_BW + cn], Bf[(2 * kp1 + 1) * STG_BW + cn]);
                unsigned bu0 = pack16(Bf[(2 * kp0) * STG_BW + 64 + cn], Bf[(2 * kp0 + 1) * STG_BW + 64 + cn]);
                unsigned bu1 = pack16(Bf[(2 * kp1) * STG_BW + 64 + cn], Bf[(2 * kp1 + 1) * STG_BW + 64 + cn]);
                mma16816(ag[0][nt], af[0], bg0, bg1);
                mma16816(ag[1][nt], af[1], bg0, bg1);
                mma16816(au[0][nt], af[0], bu0, bu1);
                mma16816(au[1][nt], af[1], bu0, bu1);
            }
        }
        __syncthreads();
    }

    const long ostride = (long)L_ * DFF;
    #pragma unroll
    for (int mt = 0; mt < 2; mt++) {
        int r0 = wm + mt * 16 + g;
        #pragma unroll
        for (int nt = 0; nt < 2; nt++) {
            int c = wn + nt * 8 + tg * 2;
            float h0 = ag[mt][nt][0] / (1.f + __expf(-ag[mt][nt][0])) * au[mt][nt][0];
            float h1 = ag[mt][nt][1] / (1.f + __expf(-ag[mt][nt][1])) * au[mt][nt][1];
            float h2 = ag[mt][nt][2] / (1.f + __expf(-ag[mt][nt][2])) * au[mt][nt][2];
            float h3 = ag[mt][nt][3] / (1.f + __expf(-ag[mt][nt][3])) * au[mt][nt][3];
            *(__half2*)(Op + (size_t)r0 * ostride + c)       = __floats2half2_rn(h0, h1);
            *(__half2*)(Op + (size_t)(r0 + 8) * ostride + c) = __floats2half2_rn(h2, h3);
        }
    }
}

// ---------------- K8: out = LN(mixed+ffn, n2); y_out = y + ffn ----------------
__global__ void k_final(const float* __restrict__ y,
                        const float* __restrict__ n2g, const float* __restrict__ n2b,
                        float* __restrict__ out) {
    int row = blockIdx.x;
    int t = threadIdx.x;
    size_t base = (size_t)row * D_ + t * 4;
    float4 f4 = *(const float4*)(g_ffn + base);
    float4 m4 = *(const float4*)(g_mixed + base);
    float4 y4 = *(const float4*)(y + base);
    float v[4] = {m4.x + f4.x, m4.y + f4.y, m4.z + f4.z, m4.w + f4.w};
    float fv[4] = {f4.x, f4.y, f4.z, f4.w};
    float yv[4] = {y4.x, y4.y, y4.z, y4.w};
    float s1 = 0.f, s2 = 0.f;
    #pragma unroll
    for (int e = 0; e < 4; e++) { s1 += v[e]; s2 += v[e] * v[e]; }
    blockReduce2_256(s1, s2);
    float m = s1 * (1.f / D_);
    float var = s2 * (1.f / D_) - m * m;
    float rs = rsqrtf(var + 1e-5f);
    #pragma unroll
    for (int e = 0; e < 4; e++) {
        int d = t * 4 + e;
        out[base + e] = (v[e] - m) * rs * n2g[d] + n2b[d];
        out[(size_t)B_ * L_ * D_ + base + e] = yv[e] + fv[e];
    }
}

// ---------------- launch ----------------
extern "C" void kernel_launch(void* const* d_in, const int* in_sizes, int n_in,
                              void* d_out, int out_size) {
    const float* x       = (const float*)d_in[0];
    const float* y       = (const float*)d_in[1];
    const float* A_log   = (const float*)d_in[2];
    const float* W_1     = (const float*)d_in[3];
    const float* W_V     = (const float*)d_in[4];
    const float* kn1_g   = (const float*)d_in[5];
    const float* kn1_b   = (const float*)d_in[6];
    const float* kn2_g   = (const float*)d_in[7];
    const float* kn2_b   = (const float*)d_in[8];
    const float* W_gate  = (const float*)d_in[9];
    const float* W_up    = (const float*)d_in[10];
    const float* W_down  = (const float*)d_in[11];
    const float* ny_g    = (const float*)d_in[12];
    const float* ny_b    = (const float*)d_in[13];
    const float* n1_g    = (const float*)d_in[14];
    const float* n1_b    = (const float*)d_in[15];
    const float* n2_g    = (const float*)d_in[16];
    const float* n2_b    = (const float*)d_in[17];
    float* out = (float*)d_out;

    static int smem_set = 0;
    if (!smem_set) {
        cudaFuncSetAttribute(k_gemm, cudaFuncAttributeMaxDynamicSharedMemorySize, G_SMEM);
        cudaFuncSetAttribute(k_gu,   cudaFuncAttributeMaxDynamicSharedMemorySize, G_SMEM);
        smem_set = 1;
    }

    k_pre<<<2048 + 256 + 128, 256>>>(x, y, ny_g, ny_b, kn1_g, kn1_b, A_log, W_1, W_V);
    k_gemm<<<dim3(N_, 1), 256, G_SMEM>>>(nullptr, 3);              // x_local (+winv)
    k_trln<<<dim3(4, B_), 256>>>(kn2_g, kn2_b);
    k_gemm<<<dim3(128, 2), 256, G_SMEM>>>(nullptr, 2);             // x_global
    k_mixed<<<B_ * L_, 256>>>(x, n1_g, n1_b);
    k_gu<<<dim3(L_, DFF / 64), 256, G_SMEM>>>(W_gate, W_up);       // gate+up+silu -> fp16 H
    k_gemm<<<dim3(L_, D_ / 128), 256, G_SMEM>>>(W_down, 1);        // down
    k_final<<<B_ * L_, 256>>>(y, n2_g, n2_b, out);
}